// round 3
// baseline (speedup 1.0000x reference)
#include <cuda_runtime.h>
#include <math.h>

#define NEMAX 200000
#define NCMAX 100000
#define NH 3
#define TILE 64
#define NT 256
#define FCHUNK 64
#define EDIM 200
#define RDIM 128
#define FEA (EDIM + RDIM)   // 328

typedef unsigned long long u64;

// ---------------- scratch (device globals; no allocation allowed) -------
__device__ float    g_gate[NH * NEMAX];
__device__ unsigned g_segmax[NH * NCMAX];
__device__ float    g_segsum[NH * NCMAX];

// ---------------- shared memory layout ----------------------------------
struct Smem {
    float bufA[FEA * TILE];     // 328*64 floats = 84 KB
    float bufB[256 * TILE];     // 64 KB
    float Ws[FCHUNK * 256];     // 64 KB weight staging
    int   idx_s[TILE];
};

enum { MODE_FC = 0, MODE_FC_RESID = 1, MODE_ADD = 2 };

// monotone float<->uint key for atomicMax on floats
__device__ __forceinline__ unsigned fkey(float f) {
    unsigned u = __float_as_uint(f);
    return (u & 0x80000000u) ? ~u : (u | 0x80000000u);
}
__device__ __forceinline__ float funkey(unsigned u) {
    return (u & 0x80000000u) ? __uint_as_float(u & 0x7FFFFFFFu)
                             : __uint_as_float(~u);
}

// Blackwell packed fp32 pair FMA (SASS FFMA2) — only reachable via PTX.
__device__ __forceinline__ void fma2(u64& d, u64 a, u64 b) {
    asm volatile("fma.rn.f32x2 %0, %1, %2, %0;" : "+l"(d) : "l"(a), "l"(b));
}
__device__ __forceinline__ u64 dup2(float x) {
    u64 r;
    unsigned xb = __float_as_uint(x);
    asm("mov.b64 %0, {%1, %1};" : "=l"(r) : "r"(xb));
    return r;
}
__device__ __forceinline__ void unpack2(u64 v, float& lo, float& hi) {
    unsigned a, b;
    asm("mov.b64 {%0, %1}, %2;" : "=r"(a), "=r"(b) : "l"(v));
    lo = __uint_as_float(a);
    hi = __uint_as_float(b);
}

// One dense layer over a 64-elem tile.
// bufIn: [F][64] feature-major, bufOut: [O][64].
// Each active thread computes an 8x8 (elem x out) register micro-tile,
// accumulated as 8x4 packed fp32 pairs along the out dim (FFMA2).
template<int MODE>
__device__ __forceinline__ void layer(const float* __restrict__ Wg,
                                      const float* __restrict__ bg,
                                      int F, int O,
                                      const float* bufIn, float* bufOut,
                                      float* Ws)
{
    const int tid = threadIdx.x;
    const int opt = O >> 3;               // o-tiles of 8
    const int te  = tid / opt;            // elem tile index
    const int to  = tid - te * opt;       // out tile index
    const bool active = (te < 8);

    u64 acc[8][4];
#pragma unroll
    for (int i = 0; i < 8; i++)
#pragma unroll
        for (int j = 0; j < 4; j++) acc[i][j] = 0ull;

    for (int f0 = 0; f0 < F; f0 += FCHUNK) {
        const int rows = min(FCHUNK, F - f0);
        __syncthreads();   // prev compute done / prev layer writes visible
        {
            const float4* src = reinterpret_cast<const float4*>(Wg + (size_t)f0 * O);
            float4* dst = reinterpret_cast<float4*>(Ws);
            const int tot4 = (rows * O) >> 2;
            for (int i = tid; i < tot4; i += NT) dst[i] = src[i];
        }
        __syncthreads();
        if (active) {
            const float* aB = bufIn + f0 * TILE + te * 8;
            const float* wB = Ws + to * 8;
#pragma unroll 2
            for (int f = 0; f < rows; ++f) {
                // a: 8 consecutive elem activations (warp-broadcast)
                float4 a0 = *reinterpret_cast<const float4*>(aB + f * TILE);
                float4 a1 = *reinterpret_cast<const float4*>(aB + f * TILE + 4);
                u64 ad[8];
                ad[0] = dup2(a0.x); ad[1] = dup2(a0.y);
                ad[2] = dup2(a0.z); ad[3] = dup2(a0.w);
                ad[4] = dup2(a1.x); ad[5] = dup2(a1.y);
                ad[6] = dup2(a1.z); ad[7] = dup2(a1.w);
                // w: 4 packed pairs (8 consecutive outs)
                ulonglong2 w01 = *reinterpret_cast<const ulonglong2*>(wB + f * O);
                ulonglong2 w23 = *reinterpret_cast<const ulonglong2*>(wB + f * O + 4);
                u64 wp[4] = { w01.x, w01.y, w23.x, w23.y };
#pragma unroll
                for (int i = 0; i < 8; i++)
#pragma unroll
                    for (int j = 0; j < 4; j++)
                        fma2(acc[i][j], ad[i], wp[j]);
            }
        }
    }

    if (active) {
        float b[8];
        if (MODE != MODE_ADD) {
#pragma unroll
            for (int j = 0; j < 8; j++) b[j] = bg[to * 8 + j];
        }
#pragma unroll
        for (int j2 = 0; j2 < 4; j2++) {
#pragma unroll
            for (int i = 0; i < 8; i++) {
                const int e = te * 8 + i;
                float vlo, vhi;
                unpack2(acc[i][j2], vlo, vhi);
                const int olo = to * 8 + j2 * 2;
                const int ohi = olo + 1;
                if (MODE == MODE_FC) {
                    vlo = fmaxf(vlo + b[j2 * 2], 0.f);
                    vhi = fmaxf(vhi + b[j2 * 2 + 1], 0.f);
                } else if (MODE == MODE_FC_RESID) {
                    vlo = fmaxf(vlo + b[j2 * 2], 0.f)     + bufIn[olo * TILE + e];
                    vhi = fmaxf(vhi + b[j2 * 2 + 1], 0.f) + bufIn[ohi * TILE + e];
                } else { // MODE_ADD: accumulate residual projection
                    vlo += bufOut[olo * TILE + e];
                    vhi += bufOut[ohi * TILE + e];
                }
                bufOut[olo * TILE + e] = vlo;
                bufOut[ohi * TILE + e] = vhi;
            }
        }
    }
}

struct P {
    const float* elem; const int* ridx; const float* remb;
    const float *fcW0, *fcb0, *fcW1, *fcb1, *fcW2, *fcb2, *fcW3, *fcb3;
    const float *fcW4, *fcb4, *fcW5, *fcb5, *fcW6, *fcb6;
    const float *resW0, *resW4, *resW6, *outW, *outb;
    int n, c;
};

__global__ void __launch_bounds__(NT, 1) mlp_kernel(P p)
{
    extern __shared__ char smraw[];
    Smem* sm = reinterpret_cast<Smem*>(smraw);
    const int h   = blockIdx.y;
    const int n0  = blockIdx.x * TILE;
    const int tid = threadIdx.x;

    if (tid < TILE)
        sm->idx_s[tid] = (n0 + tid < p.n) ? p.ridx[n0 + tid] : 0;
    __syncthreads();

    // build fea = [orig_elem_fea | reaction_embed[idx]] feature-major into bufA
    for (int i = tid; i < TILE * FEA; i += NT) {
        const int e = i / FEA;
        const int f = i - e * FEA;
        float v = 0.f;
        if (n0 + e < p.n) {
            v = (f < EDIM) ? p.elem[(size_t)(n0 + e) * EDIM + f]
                           : p.remb[(size_t)sm->idx_s[e] * RDIM + (f - EDIM)];
        }
        sm->bufA[f * TILE + e] = v;
    }
    // (layer() begins with __syncthreads, covering the hazard above)

    layer<MODE_FC>      (p.fcW0  + (size_t)h * FEA * 256, p.fcb0 + h * 256, FEA, 256, sm->bufA, sm->bufB, sm->Ws);
    layer<MODE_ADD>     (p.resW0 + (size_t)h * FEA * 256, nullptr,          FEA, 256, sm->bufA, sm->bufB, sm->Ws);
    layer<MODE_FC_RESID>(p.fcW1  + (size_t)h * 256 * 256, p.fcb1 + h * 256, 256, 256, sm->bufB, sm->bufA, sm->Ws);
    layer<MODE_FC_RESID>(p.fcW2  + (size_t)h * 256 * 256, p.fcb2 + h * 256, 256, 256, sm->bufA, sm->bufB, sm->Ws);
    layer<MODE_FC_RESID>(p.fcW3  + (size_t)h * 256 * 256, p.fcb3 + h * 256, 256, 256, sm->bufB, sm->bufA, sm->Ws);
    layer<MODE_FC>      (p.fcW4  + (size_t)h * 256 * 128, p.fcb4 + h * 128, 256, 128, sm->bufA, sm->bufB, sm->Ws);
    layer<MODE_ADD>     (p.resW4 + (size_t)h * 256 * 128, nullptr,          256, 128, sm->bufA, sm->bufB, sm->Ws);
    layer<MODE_FC_RESID>(p.fcW5  + (size_t)h * 128 * 128, p.fcb5 + h * 128, 128, 128, sm->bufB, sm->bufA, sm->Ws);
    layer<MODE_FC>      (p.fcW6  + (size_t)h * 128 * 64,  p.fcb6 + h * 64,  128,  64, sm->bufA, sm->bufB, sm->Ws);
    layer<MODE_ADD>     (p.resW6 + (size_t)h * 128 * 64,  nullptr,          128,  64, sm->bufA, sm->bufB, sm->Ws);
    __syncthreads();

    // final h vector (64 feats) lives in bufB; compute gate per elem
    if (tid < TILE && n0 + tid < p.n) {
        const int e = tid;
        float accv = 0.f;
        const float* ow = p.outW + h * 64;
#pragma unroll
        for (int f = 0; f < 64; ++f)
            accv = fmaf(sm->bufB[f * TILE + e], ow[f], accv);
        const float gate = accv + p.outb[h];
        const int gi = h * p.n + (n0 + e);
        g_gate[gi] = gate;
        atomicMax(&g_segmax[h * p.c + sm->idx_s[e]], fkey(gate));
    }
}

__global__ void init_seg(int total)
{
    const int i = blockIdx.x * blockDim.x + threadIdx.x;
    if (i < total) { g_segmax[i] = 0u; g_segsum[i] = 0.f; }
}

__global__ void exp_kernel(const int* __restrict__ ridx, int n, int c)
{
    const int i = blockIdx.x * blockDim.x + threadIdx.x;
    if (i >= NH * n) return;
    const int hh = i / n;
    const int nn = i - hh * n;
    const int r  = ridx[nn];
    const float m = funkey(g_segmax[hh * c + r]);
    const float e = expf(g_gate[i] - m);
    g_gate[i] = e;
    atomicAdd(&g_segsum[hh * c + r], e);
}

__global__ void out_kernel(const int* __restrict__ ridx,
                           float* __restrict__ out, int n, int c)
{
    const int nn = blockIdx.x * blockDim.x + threadIdx.x;
    if (nn >= n) return;
    const int r = ridx[nn];
    float s = 0.f;
#pragma unroll
    for (int hh = 0; hh < NH; ++hh)
        s += g_gate[hh * n + nn] / (g_segsum[hh * c + r] + 1e-13f);
    out[nn] = s * (1.0f / 3.0f);
}

extern "C" void kernel_launch(void* const* d_in, const int* in_sizes, int n_in,
                              void* d_out, int out_size)
{
    P p;
    p.elem  = (const float*)d_in[0];
    p.ridx  = (const int*)  d_in[1];
    p.remb  = (const float*)d_in[2];
    p.fcW0  = (const float*)d_in[3];  p.fcb0 = (const float*)d_in[4];
    p.fcW1  = (const float*)d_in[5];  p.fcb1 = (const float*)d_in[6];
    p.fcW2  = (const float*)d_in[7];  p.fcb2 = (const float*)d_in[8];
    p.fcW3  = (const float*)d_in[9];  p.fcb3 = (const float*)d_in[10];
    p.fcW4  = (const float*)d_in[11]; p.fcb4 = (const float*)d_in[12];
    p.fcW5  = (const float*)d_in[13]; p.fcb5 = (const float*)d_in[14];
    p.fcW6  = (const float*)d_in[15]; p.fcb6 = (const float*)d_in[16];
    p.resW0 = (const float*)d_in[17];
    p.resW4 = (const float*)d_in[18];
    p.resW6 = (const float*)d_in[19];
    p.outW  = (const float*)d_in[20];
    p.outb  = (const float*)d_in[21];
    p.n = in_sizes[1];            // N elems
    p.c = in_sizes[2] / RDIM;     // N reactions

    static bool smem_set = false;
    if (!smem_set) {
        cudaFuncSetAttribute(mlp_kernel,
                             cudaFuncAttributeMaxDynamicSharedMemorySize,
                             (int)sizeof(Smem));
        smem_set = true;
    }

    const int segs = NH * p.c;
    init_seg<<<(segs + 255) / 256, 256>>>(segs);

    dim3 grid((p.n + TILE - 1) / TILE, NH);
    mlp_kernel<<<grid, NT, sizeof(Smem)>>>(p);

    const int tot = NH * p.n;
    exp_kernel<<<(tot + 255) / 256, 256>>>(p.ridx, p.n, p.c);
    out_kernel<<<(p.n + 255) / 256, 256>>>(p.ridx, (float*)d_out, p.n, p.c);
}

// round 5
// speedup vs baseline: 1.6021x; 1.6021x over previous
#include <cuda_runtime.h>
#include <cuda_bf16.h>
#include <math.h>
#include <stdint.h>

typedef uint32_t u32;

#define NH 3
#define NEMAX 200000
#define NCMAX 100000

// ---------------- device scratch -----------------------------------------
__device__ float    g_gate[NH * NEMAX];
__device__ unsigned g_segmax[NH * NCMAX];
__device__ float    g_segsum[NH * NCMAX];

// prepped weights: per head, 10 matrices, blocks [kc,nb][2 planes][nrows][72]
#define HEADSZ 1105920
#define M0 0
#define M1 221184
#define M2 442368
#define M3 589824
#define M4 737280
#define M5 884736
#define M6 958464
#define M7 1032192
#define M8 1069056
#define M9 1087488
__device__ __align__(16) __nv_bfloat16 g_w[3 * HEADSZ];

// ---------------- smem layout (bytes) -------------------------------------
#define AST     528                 // A plane row stride (264 bf16)
#define APLANE  67584               // bytes per A plane (128 rows)
#define OFF_AH  0
#define OFF_AL  67584
#define OFF_W   135168              // weight staging area (up to 73728 B)
#define OFF_A0  172032              // layer0 input chunk: hi [128][72], lo +18432
#define OFF_IDX 208896
#define SMEMSZ  209408

// ---------------- helpers -------------------------------------------------
__device__ __forceinline__ u32 smem_u32(const void* p) {
    u32 a;
    asm("{ .reg .u64 t; cvta.to.shared.u64 t, %1; cvt.u32.u64 %0, t; }" : "=r"(a) : "l"(p));
    return a;
}
__device__ __forceinline__ u32 lds32(u32 a) {
    u32 v; asm volatile("ld.shared.b32 %0, [%1];" : "=r"(v) : "r"(a)); return v;
}
__device__ __forceinline__ void sts32(u32 a, u32 v) {
    asm volatile("st.shared.b32 [%0], %1;" :: "r"(a), "r"(v) : "memory");
}
__device__ __forceinline__ void cp16(u32 dst, const void* src) {
    asm volatile("cp.async.cg.shared.global [%0], [%1], 16;" :: "r"(dst), "l"(src));
}
#define CP_WAIT() asm volatile("cp.async.commit_group;\n\tcp.async.wait_group 0;" ::: "memory")

__device__ __forceinline__ void mma_bf16(float c[4], const u32 a[4], u32 b0, u32 b1) {
    asm volatile(
        "mma.sync.aligned.m16n8k16.row.col.f32.bf16.bf16.f32 "
        "{%0,%1,%2,%3}, {%4,%5,%6,%7}, {%8,%9}, {%0,%1,%2,%3};"
        : "+f"(c[0]), "+f"(c[1]), "+f"(c[2]), "+f"(c[3])
        : "r"(a[0]), "r"(a[1]), "r"(a[2]), "r"(a[3]), "r"(b0), "r"(b1));
}

__device__ __forceinline__ float bflo(u32 v) {
    return __bfloat162float(__ushort_as_bfloat16((unsigned short)(v & 0xFFFF)));
}
__device__ __forceinline__ float bfhi(u32 v) {
    return __bfloat162float(__ushort_as_bfloat16((unsigned short)(v >> 16)));
}
__device__ __forceinline__ void split2(float v0, float v1, u32& hi, u32& lo) {
    __nv_bfloat16 h0 = __float2bfloat16(v0);
    __nv_bfloat16 h1 = __float2bfloat16(v1);
    __nv_bfloat16 l0 = __float2bfloat16(v0 - __bfloat162float(h0));
    __nv_bfloat16 l1 = __float2bfloat16(v1 - __bfloat162float(h1));
    hi = (u32)__bfloat16_as_ushort(h0) | ((u32)__bfloat16_as_ushort(h1) << 16);
    lo = (u32)__bfloat16_as_ushort(l0) | ((u32)__bfloat16_as_ushort(l1) << 16);
}
__device__ __forceinline__ unsigned fkey(float f) {
    unsigned u = __float_as_uint(f);
    return (u & 0x80000000u) ? ~u : (u | 0x80000000u);
}
__device__ __forceinline__ float funkey(unsigned u) {
    return (u & 0x80000000u) ? __uint_as_float(u & 0x7FFFFFFFu) : __uint_as_float(~u);
}

// stage `bytes` (16B multiple) of prepped weights into smem
__device__ __forceinline__ void stage(u32 sdst, const __nv_bfloat16* src, int bytes, int tid) {
    const char* s = (const char*)src;
    for (int i = tid * 16; i < bytes; i += 256 * 16) cp16(sdst + i, s + i);
}

// compute one staged 64-K chunk: NT n-tiles, optional dual (fc+res) matrices
template<int NT, bool DUAL>
__device__ __forceinline__ void chunk_mma(float accF[][4], float accR[][4],
                                          u32 aHi, u32 aLo, int astride,
                                          u32 wF, u32 wR, int planeSize,
                                          int g, int t)
{
#pragma unroll
    for (int kt = 0; kt < 4; kt++) {
        const int ko = kt * 32;        // klocal*2 bytes
        u32 aH[4], aL[4];
        aH[0] = lds32(aHi + ko);            aH[1] = lds32(aHi + 8 * astride + ko);
        aH[2] = lds32(aHi + ko + 16);       aH[3] = lds32(aHi + 8 * astride + ko + 16);
        aL[0] = lds32(aLo + ko);            aL[1] = lds32(aLo + 8 * astride + ko);
        aL[2] = lds32(aLo + ko + 16);       aL[3] = lds32(aLo + 8 * astride + ko + 16);
#pragma unroll
        for (int nt = 0; nt < NT; nt++) {
            u32 ad = wF + (u32)(nt * 8 + g) * 144 + t * 4 + ko;
            u32 bh0 = lds32(ad), bh1 = lds32(ad + 16);
            u32 bl0 = lds32(ad + planeSize), bl1 = lds32(ad + planeSize + 16);
            mma_bf16(accF[nt], aH, bh0, bh1);
            mma_bf16(accF[nt], aL, bh0, bh1);
            mma_bf16(accF[nt], aH, bl0, bl1);
            if (DUAL) {
                u32 rd = wR + (u32)(nt * 8 + g) * 144 + t * 4 + ko;
                u32 rh0 = lds32(rd), rh1 = lds32(rd + 16);
                u32 rl0 = lds32(rd + planeSize), rl1 = lds32(rd + planeSize + 16);
                mma_bf16(accR[nt], aH, rh0, rh1);
                mma_bf16(accR[nt], aL, rh0, rh1);
                mma_bf16(accR[nt], aH, rl0, rl1);
            }
        }
    }
}

// epilogue: DUAL => res from accR; else identity residual from A planes
template<int NT, bool DUAL>
__device__ __forceinline__ void epilogue(float accF[][4], float accR[][4],
                                         const float* bias, u32 ahb, int colbase, int t)
{
#pragma unroll
    for (int nt = 0; nt < NT; nt++) {
        const int c0 = colbase + nt * 8 + t * 2;
        const float b0 = __ldg(bias + c0), b1 = __ldg(bias + c0 + 1);
        const u32 a0 = ahb + (u32)c0 * 2;         // row rowg
        const u32 a1 = a0 + 8 * AST;              // row rowg+8
        float v0 = fmaxf(accF[nt][0] + b0, 0.f);
        float v1 = fmaxf(accF[nt][1] + b1, 0.f);
        float v2 = fmaxf(accF[nt][2] + b0, 0.f);
        float v3 = fmaxf(accF[nt][3] + b1, 0.f);
        if (DUAL) {
            v0 += accR[nt][0]; v1 += accR[nt][1]; v2 += accR[nt][2]; v3 += accR[nt][3];
        } else {
            u32 ph0 = lds32(a0), pl0 = lds32(a0 + APLANE);
            u32 ph1 = lds32(a1), pl1 = lds32(a1 + APLANE);
            v0 += bflo(ph0) + bflo(pl0); v1 += bfhi(ph0) + bfhi(pl0);
            v2 += bflo(ph1) + bflo(pl1); v3 += bfhi(ph1) + bfhi(pl1);
        }
        u32 h, l;
        split2(v0, v1, h, l); sts32(a0, h); sts32(a0 + APLANE, l);
        split2(v2, v3, h, l); sts32(a1, h); sts32(a1 + APLANE, l);
    }
}

struct P {
    const float* elem; const int* ridx; const float* remb;
    const float *fcW0, *fcb0, *fcW1, *fcb1, *fcW2, *fcb2, *fcW3, *fcb3;
    const float *fcW4, *fcb4, *fcW5, *fcb5, *fcW6, *fcb6;
    const float *resW0, *resW4, *resW6, *outW, *outb;
    int n, c;
};

// ---------------- weight prep ----------------------------------------------
// g_w per matrix: [kc*nblocks+nb][plane][nrows][72], k-pad + transpose + split
__global__ void prep_kernel(P p)
{
    const int s = blockIdx.x * 256 + threadIdx.x;    // slot within head
    const int h = blockIdx.y;
    if (s >= 552960) return;
    const int cum[11] = {0,110592,221184,294912,368640,442368,479232,516096,534528,543744,552960};
    int m = 0;
    while (s >= cum[m + 1]) m++;
    const int r = s - cum[m];
    int K, N, nblocks, nrows, moff; const float* W;
    switch (m) {
        case 0: K=328;N=256;nblocks=4;nrows=64;  moff=M0; W=p.fcW0;  break;
        case 1: K=328;N=256;nblocks=4;nrows=64;  moff=M1; W=p.resW0; break;
        case 2: K=256;N=256;nblocks=1;nrows=256; moff=M2; W=p.fcW1;  break;
        case 3: K=256;N=256;nblocks=1;nrows=256; moff=M3; W=p.fcW2;  break;
        case 4: K=256;N=256;nblocks=1;nrows=256; moff=M4; W=p.fcW3;  break;
        case 5: K=256;N=128;nblocks=1;nrows=128; moff=M5; W=p.fcW4;  break;
        case 6: K=256;N=128;nblocks=1;nrows=128; moff=M6; W=p.resW4; break;
        case 7: K=128;N=128;nblocks=1;nrows=128; moff=M7; W=p.fcW5;  break;
        case 8: K=128;N=64; nblocks=1;nrows=64;  moff=M8; W=p.fcW6;  break;
        default:K=128;N=64; nblocks=1;nrows=64;  moff=M9; W=p.resW6; break;
    }
    const int k72 = r % 72;
    const int r1  = r / 72;
    const int nl  = r1 % nrows;
    const int r2  = r1 / nrows;
    const int nb  = r2 % nblocks;
    const int kc  = r2 / nblocks;
    const int k   = kc * 64 + k72;
    const int n   = nb * nrows + nl;
    float v = (k72 < 64 && k < K) ? W[(size_t)h * K * N + (size_t)k * N + n] : 0.f;
    __nv_bfloat16 bh = __float2bfloat16(v);
    __nv_bfloat16 bl = __float2bfloat16(v - __bfloat162float(bh));
    size_t base = (size_t)h * HEADSZ + moff
                + (size_t)(kc * nblocks + nb) * 2 * nrows * 72 + (size_t)nl * 72 + k72;
    g_w[base] = bh;
    g_w[base + (size_t)nrows * 72] = bl;
}

// ---------------- main fused MLP (mma.sync) --------------------------------
__global__ void __launch_bounds__(256, 1) mlp_tc(P p)
{
    extern __shared__ char sm[];
    const u32 sb  = smem_u32(sm);
    const int tid = threadIdx.x;
    const int lane = tid & 31, warp = tid >> 5;
    const int g = lane >> 2, t = lane & 3;
    const int h  = blockIdx.y;
    const int n0 = blockIdx.x * 128;
    const int rowg = warp * 16 + g;

    int* idx_s = (int*)(sm + OFF_IDX);
    if (tid < 128) idx_s[tid] = (n0 + tid < p.n) ? p.ridx[n0 + tid] : 0;
    __syncthreads();

    const __nv_bfloat16* gwh = g_w + (size_t)h * HEADSZ;
    const u32 ahb  = sb + OFF_AH + (u32)rowg * AST;         // A hi row base (no t)
    const u32 aHiP = ahb + t * 4;                           // frag base, main planes
    const u32 aLoP = aHiP + APLANE;
    const u32 a0Hi = sb + OFF_A0 + (u32)rowg * 144 + t * 4; // frag base, layer0 chunk
    const u32 a0Lo = a0Hi + 18432;

    // ================= layer 0: fea(384 pad) -> 256, fc + res ==============
    for (int q = 0; q < 4; q++) {
        float accF[8][4], accR[8][4];
#pragma unroll
        for (int i = 0; i < 8; i++)
#pragma unroll
            for (int j = 0; j < 4; j++) { accF[i][j] = 0.f; accR[i][j] = 0.f; }
        for (int kc = 0; kc < 6; kc++) {
            __syncthreads();
            // build layer0 input chunk (gather + split)
            for (int i = tid; i < 128 * 72; i += 256) {
                const int row = i / 72, k72 = i - row * 72;
                const int f = kc * 64 + k72;
                float v = 0.f;
                const int e = n0 + row;
                if (k72 < 64 && e < p.n) {
                    if (f < 200)      v = p.elem[(size_t)e * 200 + f];
                    else if (f < 328) v = p.remb[(size_t)idx_s[row] * 128 + (f - 200)];
                }
                __nv_bfloat16 bh = __float2bfloat16(v);
                __nv_bfloat16 bl = __float2bfloat16(v - __bfloat162float(bh));
                *(__nv_bfloat16*)(sm + OFF_A0 + row * 144 + k72 * 2) = bh;
                *(__nv_bfloat16*)(sm + OFF_A0 + 18432 + row * 144 + k72 * 2) = bl;
            }
            stage(sb + OFF_W,         gwh + M0 + (size_t)(kc * 4 + q) * 9216, 18432, tid);
            stage(sb + OFF_W + 18432, gwh + M1 + (size_t)(kc * 4 + q) * 9216, 18432, tid);
            CP_WAIT();
            __syncthreads();
            chunk_mma<8, true>(accF, accR, a0Hi, a0Lo, 144,
                               sb + OFF_W, sb + OFF_W + 18432, 9216, g, t);
        }
        epilogue<8, true>(accF, accR, p.fcb0 + h * 256, ahb, q * 64, t);
    }

    // ================= layers 1-3: 256 -> 256, identity residual ===========
    for (int l = 0; l < 3; l++) {
        const float* bias = (l == 0 ? p.fcb1 : l == 1 ? p.fcb2 : p.fcb3) + h * 256;
        const __nv_bfloat16* wl = gwh + M2 + (size_t)l * 147456;
        float acc[32][4];
#pragma unroll
        for (int i = 0; i < 32; i++)
#pragma unroll
            for (int j = 0; j < 4; j++) acc[i][j] = 0.f;
        for (int kc = 0; kc < 4; kc++) {
            __syncthreads();
            stage(sb + OFF_W, wl + (size_t)kc * 36864, 73728, tid);
            CP_WAIT();
            __syncthreads();
            chunk_mma<32, false>(acc, acc, aHiP + kc * 128, aLoP + kc * 128, AST,
                                 sb + OFF_W, 0, 36864, g, t);
        }
        __syncthreads();     // all reads of prev A done before epilogue rewrites
        epilogue<32, false>(acc, acc, bias, ahb, 0, t);
    }

    // ================= layer 4: 256 -> 128, fc + res ========================
    {
        float accF[16][4], accR[16][4];
#pragma unroll
        for (int i = 0; i < 16; i++)
#pragma unroll
            for (int j = 0; j < 4; j++) { accF[i][j] = 0.f; accR[i][j] = 0.f; }
        for (int kc = 0; kc < 4; kc++) {
            __syncthreads();
            stage(sb + OFF_W,         gwh + M5 + (size_t)kc * 18432, 36864, tid);
            stage(sb + OFF_W + 36864, gwh + M6 + (size_t)kc * 18432, 36864, tid);
            CP_WAIT();
            __syncthreads();
            chunk_mma<16, true>(accF, accR, aHiP + kc * 128, aLoP + kc * 128, AST,
                                sb + OFF_W, sb + OFF_W + 36864, 18432, g, t);
        }
        __syncthreads();
        epilogue<16, true>(accF, accR, p.fcb4 + h * 128, ahb, 0, t);
    }

    // ================= layer 5: 128 -> 128, identity ========================
    {
        float acc[16][4];
#pragma unroll
        for (int i = 0; i < 16; i++)
#pragma unroll
            for (int j = 0; j < 4; j++) acc[i][j] = 0.f;
        for (int kc = 0; kc < 2; kc++) {
            __syncthreads();
            stage(sb + OFF_W, gwh + M7 + (size_t)kc * 18432, 36864, tid);
            CP_WAIT();
            __syncthreads();
            chunk_mma<16, false>(acc, acc, aHiP + kc * 128, aLoP + kc * 128, AST,
                                 sb + OFF_W, 0, 18432, g, t);
        }
        __syncthreads();
        epilogue<16, false>(acc, acc, p.fcb5 + h * 128, ahb, 0, t);
    }

    // ================= layer 6: 128 -> 64, fc + res =========================
    {
        float accF[8][4], accR[8][4];
#pragma unroll
        for (int i = 0; i < 8; i++)
#pragma unroll
            for (int j = 0; j < 4; j++) { accF[i][j] = 0.f; accR[i][j] = 0.f; }
        for (int kc = 0; kc < 2; kc++) {
            __syncthreads();
            stage(sb + OFF_W,         gwh + M8 + (size_t)kc * 9216, 18432, tid);
            stage(sb + OFF_W + 18432, gwh + M9 + (size_t)kc * 9216, 18432, tid);
            CP_WAIT();
            __syncthreads();
            chunk_mma<8, true>(accF, accR, aHiP + kc * 128, aLoP + kc * 128, AST,
                               sb + OFF_W, sb + OFF_W + 18432, 9216, g, t);
        }
        __syncthreads();
        epilogue<8, true>(accF, accR, p.fcb6 + h * 64, ahb, 0, t);
    }
    __syncthreads();

    // ================= output head + gate ==================================
    if (tid < 128) {
        const int r = tid, e = n0 + r;
        if (e < p.n) {
            const u32 rb = sb + OFF_AH + (u32)r * AST;
            float acc = 0.f;
#pragma unroll
            for (int c = 0; c < 64; c += 2) {
                u32 ph = lds32(rb + c * 2), pl = lds32(rb + c * 2 + APLANE);
                acc = fmaf(bflo(ph) + bflo(pl), __ldg(p.outW + h * 64 + c), acc);
                acc = fmaf(bfhi(ph) + bfhi(pl), __ldg(p.outW + h * 64 + c + 1), acc);
            }
            const float gate = acc + __ldg(p.outb + h);
            g_gate[h * p.n + e] = gate;
            atomicMax(&g_segmax[h * p.c + idx_s[r]], fkey(gate));
        }
    }
}

// ---------------- segment softmax epilogue ---------------------------------
__global__ void init_seg(int total)
{
    const int i = blockIdx.x * blockDim.x + threadIdx.x;
    if (i < total) { g_segmax[i] = 0u; g_segsum[i] = 0.f; }
}

__global__ void exp_kernel(const int* __restrict__ ridx, int n, int c)
{
    const int i = blockIdx.x * blockDim.x + threadIdx.x;
    if (i >= NH * n) return;
    const int hh = i / n;
    const int nn = i - hh * n;
    const int r  = ridx[nn];
    const float m = funkey(g_segmax[hh * c + r]);
    const float e = expf(g_gate[i] - m);
    g_gate[i] = e;
    atomicAdd(&g_segsum[hh * c + r], e);
}

__global__ void out_kernel(const int* __restrict__ ridx,
                           float* __restrict__ out, int n, int c)
{
    const int nn = blockIdx.x * blockDim.x + threadIdx.x;
    if (nn >= n) return;
    const int r = ridx[nn];
    float s = 0.f;
#pragma unroll
    for (int hh = 0; hh < NH; ++hh)
        s += g_gate[hh * n + nn] / (g_segsum[hh * c + r] + 1e-13f);
    out[nn] = s * (1.0f / 3.0f);
}

extern "C" void kernel_launch(void* const* d_in, const int* in_sizes, int n_in,
                              void* d_out, int out_size)
{
    P p;
    p.elem  = (const float*)d_in[0];
    p.ridx  = (const int*)  d_in[1];
    p.remb  = (const float*)d_in[2];
    p.fcW0  = (const float*)d_in[3];  p.fcb0 = (const float*)d_in[4];
    p.fcW1  = (const float*)d_in[5];  p.fcb1 = (const float*)d_in[6];
    p.fcW2  = (const float*)d_in[7];  p.fcb2 = (const float*)d_in[8];
    p.fcW3  = (const float*)d_in[9];  p.fcb3 = (const float*)d_in[10];
    p.fcW4  = (const float*)d_in[11]; p.fcb4 = (const float*)d_in[12];
    p.fcW5  = (const float*)d_in[13]; p.fcb5 = (const float*)d_in[14];
    p.fcW6  = (const float*)d_in[15]; p.fcb6 = (const float*)d_in[16];
    p.resW0 = (const float*)d_in[17];
    p.resW4 = (const float*)d_in[18];
    p.resW6 = (const float*)d_in[19];
    p.outW  = (const float*)d_in[20];
    p.outb  = (const float*)d_in[21];
    p.n = in_sizes[1];
    p.c = in_sizes[2] / 128;

    static bool init_done = false;
    if (!init_done) {
        cudaFuncSetAttribute(mlp_tc, cudaFuncAttributeMaxDynamicSharedMemorySize, SMEMSZ);
        init_done = true;
    }

    dim3 pgrid(552960 / 256, NH);
    prep_kernel<<<pgrid, 256>>>(p);

    const int segs = NH * p.c;
    init_seg<<<(segs + 255) / 256, 256>>>(segs);

    dim3 grid((p.n + 127) / 128, NH);
    mlp_tc<<<grid, 256, SMEMSZ>>>(p);

    const int tot = NH * p.n;
    exp_kernel<<<(tot + 255) / 256, 256>>>(p.ridx, p.n, p.c);
    out_kernel<<<(p.n + 255) / 256, 256>>>(p.ridx, (float*)d_out, p.n, p.c);
}

// round 6
// speedup vs baseline: 3.7224x; 2.3235x over previous
#include <cuda_runtime.h>
#include <cuda_bf16.h>
#include <math.h>
#include <stdint.h>

typedef uint32_t u32;

#define NH 3
#define NEMAX 200000
#define NCMAX 100000
#define BLKMAX 1563          // ceil(200000/128)

// ---------------- device scratch -----------------------------------------
__device__ float    g_gate[NH * NEMAX];
__device__ unsigned g_segmax[NH * NCMAX];
__device__ float    g_segsum[NH * NCMAX];

// frag-packed weights, per head 983040 bf16 (byte stride HB)
#define HB 1966080
__device__ __align__(16) __nv_bfloat16 g_w[3 * 983040];
// frag-packed layer0 activations: per block 196608 B (hi plane 98304 + lo plane)
__device__ uint4 g_a0[(size_t)BLKMAX * 12288];

// matrix byte offsets within a head
#define B0 0
#define B1 393216
#define B2 786432
#define B5 1572864
#define B6 1703936
#define B7 1835008
#define B8 1900544
#define B9 1933312

// ---------------- smem offsets (bytes) -------------------------------------
#define APL     65536        // A plane size
#define OFF_AH  0
#define OFF_AL  65536
#define OFF_W   131072       // weight stage (65536)
#define OFF_A0H 196608       // layer0 A chunk hi (16384)
#define OFF_A0L 212992       // layer0 A chunk lo (16384)
#define OFF_IDX 229376
#define SMEMSZ  229888

// ---------------- helpers -------------------------------------------------
__device__ __forceinline__ u32 smem_u32(const void* p) {
    u32 a;
    asm("{ .reg .u64 t; cvta.to.shared.u64 t, %1; cvt.u32.u64 %0, t; }" : "=r"(a) : "l"(p));
    return a;
}
__device__ __forceinline__ u32 lds32(u32 a) {
    u32 v; asm volatile("ld.shared.b32 %0, [%1];" : "=r"(v) : "r"(a)); return v;
}
__device__ __forceinline__ uint4 lds128(u32 a) {
    uint4 v;
    asm volatile("ld.shared.v4.b32 {%0,%1,%2,%3}, [%4];"
                 : "=r"(v.x), "=r"(v.y), "=r"(v.z), "=r"(v.w) : "r"(a));
    return v;
}
__device__ __forceinline__ void sts32(u32 a, u32 v) {
    asm volatile("st.shared.b32 [%0], %1;" :: "r"(a), "r"(v) : "memory");
}
__device__ __forceinline__ void cp16(u32 dst, const void* src) {
    asm volatile("cp.async.cg.shared.global [%0], [%1], 16;" :: "r"(dst), "l"(src));
}
#define CP_WAIT() asm volatile("cp.async.commit_group;\n\tcp.async.wait_group 0;" ::: "memory")

__device__ __forceinline__ void mma_bf16(float c[4], const u32 a[4], u32 b0, u32 b1) {
    asm volatile(
        "mma.sync.aligned.m16n8k16.row.col.f32.bf16.bf16.f32 "
        "{%0,%1,%2,%3}, {%4,%5,%6,%7}, {%8,%9}, {%0,%1,%2,%3};"
        : "+f"(c[0]), "+f"(c[1]), "+f"(c[2]), "+f"(c[3])
        : "r"(a[0]), "r"(a[1]), "r"(a[2]), "r"(a[3]), "r"(b0), "r"(b1));
}

__device__ __forceinline__ float bflo(u32 v) {
    return __bfloat162float(__ushort_as_bfloat16((unsigned short)(v & 0xFFFF)));
}
__device__ __forceinline__ float bfhi(u32 v) {
    return __bfloat162float(__ushort_as_bfloat16((unsigned short)(v >> 16)));
}
__device__ __forceinline__ void split2(float v0, float v1, u32& hi, u32& lo) {
    __nv_bfloat16 h0 = __float2bfloat16(v0);
    __nv_bfloat16 h1 = __float2bfloat16(v1);
    __nv_bfloat16 l0 = __float2bfloat16(v0 - __bfloat162float(h0));
    __nv_bfloat16 l1 = __float2bfloat16(v1 - __bfloat162float(h1));
    hi = (u32)__bfloat16_as_ushort(h0) | ((u32)__bfloat16_as_ushort(h1) << 16);
    lo = (u32)__bfloat16_as_ushort(l0) | ((u32)__bfloat16_as_ushort(l1) << 16);
}
__device__ __forceinline__ unsigned fkey(float f) {
    unsigned u = __float_as_uint(f);
    return (u & 0x80000000u) ? ~u : (u | 0x80000000u);
}
__device__ __forceinline__ float funkey(unsigned u) {
    return (u & 0x80000000u) ? __uint_as_float(u & 0x7FFFFFFFu) : __uint_as_float(~u);
}

__device__ __forceinline__ void stage(u32 sdst, const void* src, int bytes, int tid) {
    const char* s = (const char*)src;
    for (int i = tid * 16; i < bytes; i += 256 * 16) cp16(sdst + i, s + i);
}

struct P {
    const float* elem; const int* ridx; const float* remb;
    const float *fcW0, *fcb0, *fcW1, *fcb1, *fcW2, *fcb2, *fcW3, *fcb3;
    const float *fcW4, *fcb4, *fcW5, *fcb5, *fcW6, *fcb6;
    const float *resW0, *resW4, *resW6, *outW, *outb;
    int n, c;
};

// ---------------- prep: weights -> frag-packed layout ----------------------
// frag uint4 = {hi(k0,k0+1), hi(k0+8,k0+9), lo(k0,k0+1), lo(k0+8,k0+9)}
__global__ void prep_w(P p)
{
    const int fid = blockIdx.x * 256 + threadIdx.x;
    const int h = blockIdx.y;
    if (fid >= 122880) return;
    const int fo[11] = {0,24576,49152,65536,81920,98304,106496,114688,118784,120832,122880};
    int m = 0;
    while (fid >= fo[m + 1]) m++;
    const int local = fid - fo[m];
    int K, N; const float* W;
    switch (m) {
        case 0: K=328; N=256; W=p.fcW0;  break;
        case 1: K=328; N=256; W=p.resW0; break;
        case 2: K=256; N=256; W=p.fcW1;  break;
        case 3: K=256; N=256; W=p.fcW2;  break;
        case 4: K=256; N=256; W=p.fcW3;  break;
        case 5: K=256; N=128; W=p.fcW4;  break;
        case 6: K=256; N=128; W=p.resW4; break;
        case 7: K=128; N=128; W=p.fcW5;  break;
        case 8: K=128; N=64;  W=p.fcW6;  break;
        default:K=128; N=64;  W=p.resW6; break;
    }
    int t, n, kt, kc;
    if (m < 2) {   // layer0: [kc][q][kt][64n][4t]
        t = local & 3;
        const int nl = (local >> 2) & 63;
        kt = (local >> 8) & 3;
        const int blkq = local >> 10;
        const int q = blkq & 3;
        kc = blkq >> 2;
        n = q * 64 + nl;
    } else {       // [kc][kt][N][4t]
        t = local & 3;
        int r = local >> 2;
        n = r % N; r /= N;
        kt = r & 3; kc = r >> 2;
    }
    const int k0 = kc * 64 + kt * 16 + 2 * t;
    const float* Wh = W + (size_t)h * K * N;
    const float v0 = (k0     < K) ? Wh[(size_t)k0 * N + n]       : 0.f;
    const float v1 = (k0 + 1 < K) ? Wh[(size_t)(k0 + 1) * N + n] : 0.f;
    const float v8 = (k0 + 8 < K) ? Wh[(size_t)(k0 + 8) * N + n] : 0.f;
    const float v9 = (k0 + 9 < K) ? Wh[(size_t)(k0 + 9) * N + n] : 0.f;
    uint4 o;
    u32 l0, l1;
    split2(v0, v1, o.x, l0);
    split2(v8, v9, o.y, l1);
    o.z = l0; o.w = l1;
    *(uint4*)((char*)g_w + (size_t)h * HB + (size_t)fid * 16) = o;
}

// ---------------- prep: layer0 input -> frag-packed g_a0 -------------------
__device__ __forceinline__ void ld2(const P& p, int e, int idx, int f, float& x, float& y)
{
    if (f < 200)      { x = p.elem[(size_t)e * 200 + f]; y = p.elem[(size_t)e * 200 + f + 1]; }
    else if (f < 328) { const float* r = p.remb + (size_t)idx * 128 + (f - 200); x = r[0]; y = r[1]; }
    else              { x = 0.f; y = 0.f; }
}

__global__ void prep_a0(P p)
{
    const int fi  = blockIdx.x * 256 + threadIdx.x;    // 0..6143
    const int blk = blockIdx.y;
    const int t  = fi & 3;
    const int g  = (fi >> 2) & 7;
    const int w  = (fi >> 5) & 7;
    const int kt = (fi >> 8) & 3;
    const int kc = fi >> 10;
    const int k0 = kc * 64 + kt * 16 + 2 * t;
    float v[2][4];
#pragma unroll
    for (int row = 0; row < 2; row++) {
        const int e = blk * 128 + w * 16 + g + row * 8;
        if (e < p.n) {
            const int idx = p.ridx[e];
            ld2(p, e, idx, k0,     v[row][0], v[row][1]);
            ld2(p, e, idx, k0 + 8, v[row][2], v[row][3]);
        } else {
            v[row][0] = v[row][1] = v[row][2] = v[row][3] = 0.f;
        }
    }
    uint4 H, L;
    split2(v[0][0], v[0][1], H.x, L.x);
    split2(v[1][0], v[1][1], H.y, L.y);
    split2(v[0][2], v[0][3], H.z, L.z);
    split2(v[1][2], v[1][3], H.w, L.w);
    char* dst = (char*)g_a0 + (size_t)blk * 196608 + (size_t)fi * 16;
    *(uint4*)dst = H;
    *(uint4*)(dst + 98304) = L;
}

// ---------------- chunk MMA (frag-packed, LDS.128) --------------------------
template<int NT, bool DUAL>
__device__ __forceinline__ void chunk_mma(float accF[][4], float accR[][4],
                                          u32 aHiB, u32 aLoB, u32 wF, u32 wR,
                                          int N, u32 fragoff, int g, int t)
{
#pragma unroll
    for (int kt = 0; kt < 4; kt++) {
        const uint4 ahv = lds128(aHiB + kt * 4096 + fragoff);
        const uint4 alv = lds128(aLoB + kt * 4096 + fragoff);
        const u32 aH[4] = {ahv.x, ahv.y, ahv.z, ahv.w};
        const u32 aL[4] = {alv.x, alv.y, alv.z, alv.w};
#pragma unroll
        for (int nt = 0; nt < NT; nt++) {
            const u32 off = (u32)(((kt * N + nt * 8 + g) * 4 + t) * 16);
            const uint4 wv = lds128(wF + off);
            mma_bf16(accF[nt], aH, wv.x, wv.y);
            mma_bf16(accF[nt], aL, wv.x, wv.y);
            mma_bf16(accF[nt], aH, wv.z, wv.w);
            if (DUAL) {
                const uint4 rv = lds128(wR + off);
                mma_bf16(accR[nt], aH, rv.x, rv.y);
                mma_bf16(accR[nt], aL, rv.x, rv.y);
                mma_bf16(accR[nt], aH, rv.z, rv.w);
            }
        }
    }
}

// ---------------- epilogue: bias+relu+residual -> frag-packed A planes ------
template<int NT, bool DUAL>
__device__ __forceinline__ void epilogue(float accF[][4], float accR[][4],
                                         const float* bias, u32 sb, int colbase,
                                         int w, int g, int t)
{
#pragma unroll
    for (int nt = 0; nt < NT; nt++) {
        const int c0 = colbase + nt * 8 + t * 2;
        const float b0 = __ldg(bias + c0), b1 = __ldg(bias + c0 + 1);
        float v0 = fmaxf(accF[nt][0] + b0, 0.f);
        float v1 = fmaxf(accF[nt][1] + b1, 0.f);
        float v2 = fmaxf(accF[nt][2] + b0, 0.f);
        float v3 = fmaxf(accF[nt][3] + b1, 0.f);
        const u32 fb = sb + OFF_AH + (u32)((c0 >> 4) * 4096)
                     + (u32)((w * 32 + g * 4 + ((c0 & 7) >> 1)) * 16) + (u32)(c0 & 8);
        if (DUAL) {
            v0 += accR[nt][0]; v1 += accR[nt][1];
            v2 += accR[nt][2]; v3 += accR[nt][3];
        } else {
            const u32 ph0 = lds32(fb),     pl0 = lds32(fb + APL);
            const u32 ph1 = lds32(fb + 4), pl1 = lds32(fb + 4 + APL);
            v0 += bflo(ph0) + bflo(pl0); v1 += bfhi(ph0) + bfhi(pl0);
            v2 += bflo(ph1) + bflo(pl1); v3 += bfhi(ph1) + bfhi(pl1);
        }
        u32 hh, ll;
        split2(v0, v1, hh, ll); sts32(fb, hh);     sts32(fb + APL, ll);
        split2(v2, v3, hh, ll); sts32(fb + 4, hh); sts32(fb + 4 + APL, ll);
    }
}

// ---------------- main fused MLP --------------------------------------------
__global__ void __launch_bounds__(256, 1) mlp_tc(P p)
{
    extern __shared__ char sm[];
    const u32 sb  = smem_u32(sm);
    const int tid = threadIdx.x;
    const int lane = tid & 31, warp = tid >> 5;
    const int g = lane >> 2, t = lane & 3;
    const int h   = blockIdx.y;
    const int blk = blockIdx.x;
    const int n0  = blk * 128;
    const u32 fragoff = (u32)((warp * 32 + lane) * 16);

    int* idx_s = (int*)(sm + OFF_IDX);
    if (tid < 128) idx_s[tid] = (n0 + tid < p.n) ? p.ridx[n0 + tid] : 0;

    const char* gw = (const char*)g_w + (size_t)h * HB;
    const char* a0 = (const char*)g_a0 + (size_t)blk * 196608;

    // ===== layer 0: 384(pad) -> 256, fc + res, n-quarters =====
    for (int q = 0; q < 4; q++) {
        float accF[8][4], accR[8][4];
#pragma unroll
        for (int i = 0; i < 8; i++)
#pragma unroll
            for (int j = 0; j < 4; j++) { accF[i][j] = 0.f; accR[i][j] = 0.f; }
        for (int kc = 0; kc < 6; kc++) {
            __syncthreads();
            stage(sb + OFF_A0H, a0 + kc * 16384,          16384, tid);
            stage(sb + OFF_A0L, a0 + 98304 + kc * 16384,  16384, tid);
            stage(sb + OFF_W,          gw + B0 + (size_t)(kc * 4 + q) * 16384, 16384, tid);
            stage(sb + OFF_W + 16384,  gw + B1 + (size_t)(kc * 4 + q) * 16384, 16384, tid);
            CP_WAIT();
            __syncthreads();
            chunk_mma<8, true>(accF, accR, sb + OFF_A0H, sb + OFF_A0L,
                               sb + OFF_W, sb + OFF_W + 16384, 64, fragoff, g, t);
        }
        epilogue<8, true>(accF, accR, p.fcb0 + h * 256, sb, q * 64, warp, g, t);
    }

    // ===== layers 1-3: 256 -> 256, identity residual =====
    for (int l = 0; l < 3; l++) {
        const float* bias = (l == 0 ? p.fcb1 : l == 1 ? p.fcb2 : p.fcb3) + h * 256;
        float acc[32][4];
#pragma unroll
        for (int i = 0; i < 32; i++)
#pragma unroll
            for (int j = 0; j < 4; j++) acc[i][j] = 0.f;
        for (int kc = 0; kc < 4; kc++) {
            __syncthreads();
            stage(sb + OFF_W, gw + B2 + (size_t)l * 262144 + (size_t)kc * 65536, 65536, tid);
            CP_WAIT();
            __syncthreads();
            chunk_mma<32, false>(acc, acc, sb + OFF_AH + kc * 16384, sb + OFF_AL + kc * 16384,
                                 sb + OFF_W, 0, 256, fragoff, g, t);
        }
        __syncthreads();
        epilogue<32, false>(acc, acc, bias, sb, 0, warp, g, t);
    }

    // ===== layer 4: 256 -> 128, fc + res =====
    {
        float accF[16][4], accR[16][4];
#pragma unroll
        for (int i = 0; i < 16; i++)
#pragma unroll
            for (int j = 0; j < 4; j++) { accF[i][j] = 0.f; accR[i][j] = 0.f; }
        for (int kc = 0; kc < 4; kc++) {
            __syncthreads();
            stage(sb + OFF_W,          gw + B5 + (size_t)kc * 32768, 32768, tid);
            stage(sb + OFF_W + 32768,  gw + B6 + (size_t)kc * 32768, 32768, tid);
            CP_WAIT();
            __syncthreads();
            chunk_mma<16, true>(accF, accR, sb + OFF_AH + kc * 16384, sb + OFF_AL + kc * 16384,
                                sb + OFF_W, sb + OFF_W + 32768, 128, fragoff, g, t);
        }
        __syncthreads();
        epilogue<16, true>(accF, accR, p.fcb4 + h * 128, sb, 0, warp, g, t);
    }

    // ===== layer 5: 128 -> 128, identity =====
    {
        float acc[16][4];
#pragma unroll
        for (int i = 0; i < 16; i++)
#pragma unroll
            for (int j = 0; j < 4; j++) acc[i][j] = 0.f;
        for (int kc = 0; kc < 2; kc++) {
            __syncthreads();
            stage(sb + OFF_W, gw + B7 + (size_t)kc * 32768, 32768, tid);
            CP_WAIT();
            __syncthreads();
            chunk_mma<16, false>(acc, acc, sb + OFF_AH + kc * 16384, sb + OFF_AL + kc * 16384,
                                 sb + OFF_W, 0, 128, fragoff, g, t);
        }
        __syncthreads();
        epilogue<16, false>(acc, acc, p.fcb5 + h * 128, sb, 0, warp, g, t);
    }

    // ===== layer 6: 128 -> 64, fc + res =====
    {
        float accF[8][4], accR[8][4];
#pragma unroll
        for (int i = 0; i < 8; i++)
#pragma unroll
            for (int j = 0; j < 4; j++) { accF[i][j] = 0.f; accR[i][j] = 0.f; }
        for (int kc = 0; kc < 2; kc++) {
            __syncthreads();
            stage(sb + OFF_W,          gw + B8 + (size_t)kc * 16384, 16384, tid);
            stage(sb + OFF_W + 16384,  gw + B9 + (size_t)kc * 16384, 16384, tid);
            CP_WAIT();
            __syncthreads();
            chunk_mma<8, true>(accF, accR, sb + OFF_AH + kc * 16384, sb + OFF_AL + kc * 16384,
                               sb + OFF_W, sb + OFF_W + 16384, 64, fragoff, g, t);
        }
        __syncthreads();
        epilogue<8, true>(accF, accR, p.fcb6 + h * 64, sb, 0, warp, g, t);
    }
    __syncthreads();

    // ===== output head: gate = h . outW + outb =====
    if (tid < 128) {
        const int r = tid, e = n0 + r;
        if (e < p.n) {
            const int w2 = r >> 4, g2 = r & 7, rh = (r & 15) >> 3;
            float acc = 0.f;
#pragma unroll
            for (int c = 0; c < 64; c += 2) {
                const u32 fb = sb + OFF_AH + (u32)((c >> 4) * 4096)
                             + (u32)((w2 * 32 + g2 * 4 + ((c & 7) >> 1)) * 16)
                             + (u32)((c & 8) + rh * 4);
                const u32 ph = lds32(fb), pl = lds32(fb + APL);
                acc = fmaf(bflo(ph) + bflo(pl), __ldg(p.outW + h * 64 + c), acc);
                acc = fmaf(bfhi(ph) + bfhi(pl), __ldg(p.outW + h * 64 + c + 1), acc);
            }
            const float gate = acc + __ldg(p.outb + h);
            g_gate[h * p.n + e] = gate;
            atomicMax(&g_segmax[h * p.c + idx_s[r]], fkey(gate));
        }
    }
}

// ---------------- segment softmax epilogue ---------------------------------
__global__ void init_seg(int total)
{
    const int i = blockIdx.x * blockDim.x + threadIdx.x;
    if (i < total) { g_segmax[i] = 0u; g_segsum[i] = 0.f; }
}

__global__ void exp_kernel(const int* __restrict__ ridx, int n, int c)
{
    const int i = blockIdx.x * blockDim.x + threadIdx.x;
    if (i >= NH * n) return;
    const int hh = i / n;
    const int nn = i - hh * n;
    const int r  = ridx[nn];
    const float m = funkey(g_segmax[hh * c + r]);
    const float e = expf(g_gate[i] - m);
    g_gate[i] = e;
    atomicAdd(&g_segsum[hh * c + r], e);
}

__global__ void out_kernel(const int* __restrict__ ridx,
                           float* __restrict__ out, int n, int c)
{
    const int nn = blockIdx.x * blockDim.x + threadIdx.x;
    if (nn >= n) return;
    const int r = ridx[nn];
    float s = 0.f;
#pragma unroll
    for (int hh = 0; hh < NH; ++hh)
        s += g_gate[hh * n + nn] / (g_segsum[hh * c + r] + 1e-13f);
    out[nn] = s * (1.0f / 3.0f);
}

extern "C" void kernel_launch(void* const* d_in, const int* in_sizes, int n_in,
                              void* d_out, int out_size)
{
    P p;
    p.elem  = (const float*)d_in[0];
    p.ridx  = (const int*)  d_in[1];
    p.remb  = (const float*)d_in[2];
    p.fcW0  = (const float*)d_in[3];  p.fcb0 = (const float*)d_in[4];
    p.fcW1  = (const float*)d_in[5];  p.fcb1 = (const float*)d_in[6];
    p.fcW2  = (const float*)d_in[7];  p.fcb2 = (const float*)d_in[8];
    p.fcW3  = (const float*)d_in[9];  p.fcb3 = (const float*)d_in[10];
    p.fcW4  = (const float*)d_in[11]; p.fcb4 = (const float*)d_in[12];
    p.fcW5  = (const float*)d_in[13]; p.fcb5 = (const float*)d_in[14];
    p.fcW6  = (const float*)d_in[15]; p.fcb6 = (const float*)d_in[16];
    p.resW0 = (const float*)d_in[17];
    p.resW4 = (const float*)d_in[18];
    p.resW6 = (const float*)d_in[19];
    p.outW  = (const float*)d_in[20];
    p.outb  = (const float*)d_in[21];
    p.n = in_sizes[1];
    p.c = in_sizes[2] / 128;

    static bool init_done = false;
    if (!init_done) {
        cudaFuncSetAttribute(mlp_tc, cudaFuncAttributeMaxDynamicSharedMemorySize, SMEMSZ);
        init_done = true;
    }

    const int nblk = (p.n + 127) / 128;

    prep_w<<<dim3(480, NH), 256>>>(p);
    prep_a0<<<dim3(24, nblk), 256>>>(p);

    const int segs = NH * p.c;
    init_seg<<<(segs + 255) / 256, 256>>>(segs);

    mlp_tc<<<dim3(nblk, NH), 256, SMEMSZ>>>(p);

    const int tot = NH * p.n;
    exp_kernel<<<(tot + 255) / 256, 256>>>(p.ridx, p.n, p.c);
    out_kernel<<<(p.n + 255) / 256, 256>>>(p.ridx, (float*)d_out, p.n, p.c);
}

// round 7
// speedup vs baseline: 3.8637x; 1.0380x over previous
#include <cuda_runtime.h>
#include <cuda_bf16.h>
#include <math.h>
#include <stdint.h>

typedef uint32_t u32;

#define NH 3
#define NEMAX 200000
#define NCMAX 100000
#define BLKMAX 1563          // ceil(200000/128)

// ---------------- device scratch -----------------------------------------
__device__ float    g_gate[NH * NEMAX];
__device__ unsigned g_segmax[NH * NCMAX];
__device__ float    g_segsum[NH * NCMAX];

// frag-packed weights, per head 983040 bf16 (byte stride HB)
#define HB 1966080
__device__ __align__(16) __nv_bfloat16 g_w[3 * 983040];
// frag-packed layer0 activations: per block 196608 B (hi plane 98304 + lo plane)
__device__ uint4 g_a0[(size_t)BLKMAX * 12288];

// matrix byte offsets within a head
#define B0 0
#define B1 393216
#define B2 786432
#define B5 1572864
#define B6 1703936
#define B7 1835008
#define B8 1900544
#define B9 1933312

// ---------------- smem offsets (bytes) -------------------------------------
#define APL     65536        // A plane size
#define OFF_AH  0
#define OFF_AL  65536
#define OFF_W   131072       // weight ping-pong, 2 x 32768
#define OFF_IDX 196608
#define SMEMSZ  197120

// ---------------- helpers -------------------------------------------------
__device__ __forceinline__ u32 smem_u32(const void* p) {
    u32 a;
    asm("{ .reg .u64 t; cvta.to.shared.u64 t, %1; cvt.u32.u64 %0, t; }" : "=r"(a) : "l"(p));
    return a;
}
__device__ __forceinline__ u32 lds32(u32 a) {
    u32 v; asm volatile("ld.shared.b32 %0, [%1];" : "=r"(v) : "r"(a)); return v;
}
__device__ __forceinline__ uint4 lds128(u32 a) {
    uint4 v;
    asm volatile("ld.shared.v4.b32 {%0,%1,%2,%3}, [%4];"
                 : "=r"(v.x), "=r"(v.y), "=r"(v.z), "=r"(v.w) : "r"(a));
    return v;
}
__device__ __forceinline__ void sts32(u32 a, u32 v) {
    asm volatile("st.shared.b32 [%0], %1;" :: "r"(a), "r"(v) : "memory");
}
__device__ __forceinline__ void cp16(u32 dst, const void* src) {
    asm volatile("cp.async.cg.shared.global [%0], [%1], 16;" :: "r"(dst), "l"(src));
}
#define COMMIT()  asm volatile("cp.async.commit_group;" ::: "memory")
#define WAITG0()  asm volatile("cp.async.wait_group 0;" ::: "memory")

__device__ __forceinline__ void mma_bf16(float c[4], const u32 a[4], u32 b0, u32 b1) {
    asm volatile(
        "mma.sync.aligned.m16n8k16.row.col.f32.bf16.bf16.f32 "
        "{%0,%1,%2,%3}, {%4,%5,%6,%7}, {%8,%9}, {%0,%1,%2,%3};"
        : "+f"(c[0]), "+f"(c[1]), "+f"(c[2]), "+f"(c[3])
        : "r"(a[0]), "r"(a[1]), "r"(a[2]), "r"(a[3]), "r"(b0), "r"(b1));
}

__device__ __forceinline__ float bflo(u32 v) {
    return __bfloat162float(__ushort_as_bfloat16((unsigned short)(v & 0xFFFF)));
}
__device__ __forceinline__ float bfhi(u32 v) {
    return __bfloat162float(__ushort_as_bfloat16((unsigned short)(v >> 16)));
}
__device__ __forceinline__ void split2(float v0, float v1, u32& hi, u32& lo) {
    __nv_bfloat16 h0 = __float2bfloat16(v0);
    __nv_bfloat16 h1 = __float2bfloat16(v1);
    __nv_bfloat16 l0 = __float2bfloat16(v0 - __bfloat162float(h0));
    __nv_bfloat16 l1 = __float2bfloat16(v1 - __bfloat162float(h1));
    hi = (u32)__bfloat16_as_ushort(h0) | ((u32)__bfloat16_as_ushort(h1) << 16);
    lo = (u32)__bfloat16_as_ushort(l0) | ((u32)__bfloat16_as_ushort(l1) << 16);
}
__device__ __forceinline__ unsigned fkey(float f) {
    unsigned u = __float_as_uint(f);
    return (u & 0x80000000u) ? ~u : (u | 0x80000000u);
}
__device__ __forceinline__ float funkey(unsigned u) {
    return (u & 0x80000000u) ? __uint_as_float(u & 0x7FFFFFFFu) : __uint_as_float(~u);
}

__device__ __forceinline__ void stage(u32 sdst, const void* src, int bytes, int tid) {
    const char* s = (const char*)src;
    for (int i = tid * 16; i < bytes; i += 256 * 16) cp16(sdst + i, s + i);
}

struct P {
    const float* elem; const int* ridx; const float* remb;
    const float *fcW0, *fcb0, *fcW1, *fcb1, *fcW2, *fcb2, *fcW3, *fcb3;
    const float *fcW4, *fcb4, *fcW5, *fcb5, *fcW6, *fcb6;
    const float *resW0, *resW4, *resW6, *outW, *outb;
    int n, c;
};

// ---------------- prep: weights -> frag-packed layout ----------------------
// frag uint4 = {hi(k0,k0+1), hi(k0+8,k0+9), lo(k0,k0+1), lo(k0+8,k0+9)}
__global__ void prep_w(P p)
{
    const int fid = blockIdx.x * 256 + threadIdx.x;
    const int h = blockIdx.y;
    if (fid >= 122880) return;
    const int fo[11] = {0,24576,49152,65536,81920,98304,106496,114688,118784,120832,122880};
    int m = 0;
    while (fid >= fo[m + 1]) m++;
    const int local = fid - fo[m];
    int K, N; const float* W;
    switch (m) {
        case 0: K=328; N=256; W=p.fcW0;  break;
        case 1: K=328; N=256; W=p.resW0; break;
        case 2: K=256; N=256; W=p.fcW1;  break;
        case 3: K=256; N=256; W=p.fcW2;  break;
        case 4: K=256; N=256; W=p.fcW3;  break;
        case 5: K=256; N=128; W=p.fcW4;  break;
        case 6: K=256; N=128; W=p.resW4; break;
        case 7: K=128; N=128; W=p.fcW5;  break;
        case 8: K=128; N=64;  W=p.fcW6;  break;
        default:K=128; N=64;  W=p.resW6; break;
    }
    int t, n, kt, kc;
    if (m < 2) {   // layer0: [kc][q][kt][64n][4t]
        t = local & 3;
        const int nl = (local >> 2) & 63;
        kt = (local >> 8) & 3;
        const int blkq = local >> 10;
        const int q = blkq & 3;
        kc = blkq >> 2;
        n = q * 64 + nl;
    } else {       // [kc][kt][N][4t]
        t = local & 3;
        int r = local >> 2;
        n = r % N; r /= N;
        kt = r & 3; kc = r >> 2;
    }
    const int k0 = kc * 64 + kt * 16 + 2 * t;
    const float* Wh = W + (size_t)h * K * N;
    const float v0 = (k0     < K) ? Wh[(size_t)k0 * N + n]       : 0.f;
    const float v1 = (k0 + 1 < K) ? Wh[(size_t)(k0 + 1) * N + n] : 0.f;
    const float v8 = (k0 + 8 < K) ? Wh[(size_t)(k0 + 8) * N + n] : 0.f;
    const float v9 = (k0 + 9 < K) ? Wh[(size_t)(k0 + 9) * N + n] : 0.f;
    uint4 o;
    u32 l0, l1;
    split2(v0, v1, o.x, l0);
    split2(v8, v9, o.y, l1);
    o.z = l0; o.w = l1;
    *(uint4*)((char*)g_w + (size_t)h * HB + (size_t)fid * 16) = o;
}

// ---------------- prep: layer0 input -> frag-packed g_a0 -------------------
__device__ __forceinline__ void ld2(const P& p, int e, int idx, int f, float& x, float& y)
{
    if (f < 200)      { x = p.elem[(size_t)e * 200 + f]; y = p.elem[(size_t)e * 200 + f + 1]; }
    else if (f < 328) { const float* r = p.remb + (size_t)idx * 128 + (f - 200); x = r[0]; y = r[1]; }
    else              { x = 0.f; y = 0.f; }
}

__global__ void prep_a0(P p)
{
    const int fi  = blockIdx.x * 256 + threadIdx.x;    // 0..6143
    const int blk = blockIdx.y;
    const int t  = fi & 3;
    const int g  = (fi >> 2) & 7;
    const int w  = (fi >> 5) & 7;
    const int kt = (fi >> 8) & 3;
    const int kc = fi >> 10;
    const int k0 = kc * 64 + kt * 16 + 2 * t;
    float v[2][4];
#pragma unroll
    for (int row = 0; row < 2; row++) {
        const int e = blk * 128 + w * 16 + g + row * 8;
        if (e < p.n) {
            const int idx = p.ridx[e];
            ld2(p, e, idx, k0,     v[row][0], v[row][1]);
            ld2(p, e, idx, k0 + 8, v[row][2], v[row][3]);
        } else {
            v[row][0] = v[row][1] = v[row][2] = v[row][3] = 0.f;
        }
    }
    uint4 H, L;
    split2(v[0][0], v[0][1], H.x, L.x);
    split2(v[1][0], v[1][1], H.y, L.y);
    split2(v[0][2], v[0][3], H.z, L.z);
    split2(v[1][2], v[1][3], H.w, L.w);
    char* dst = (char*)g_a0 + (size_t)blk * 196608 + (size_t)fi * 16;
    *(uint4*)dst = H;
    *(uint4*)(dst + 98304) = L;
}

// ---------------- chunk MMA (A from smem planes) ----------------------------
template<int KT, int NT, bool DUAL>
__device__ __forceinline__ void mma_chunk_s(float accF[][4], float accR[][4],
                                            u32 abase, u32 wF, u32 wR,
                                            int N, int g, int t)
{
#pragma unroll
    for (int kt = 0; kt < KT; kt++) {
        const uint4 ahv = lds128(abase + kt * 4096);
        const uint4 alv = lds128(abase + kt * 4096 + APL);
        const u32 aH[4] = {ahv.x, ahv.y, ahv.z, ahv.w};
        const u32 aL[4] = {alv.x, alv.y, alv.z, alv.w};
#pragma unroll
        for (int nt = 0; nt < NT; nt++) {
            const u32 off = (u32)(((kt * N + nt * 8 + g) * 4 + t) * 16);
            const uint4 wv = lds128(wF + off);
            mma_bf16(accF[nt], aH, wv.x, wv.y);
            mma_bf16(accF[nt], aL, wv.x, wv.y);
            mma_bf16(accF[nt], aH, wv.z, wv.w);
            if (DUAL) {
                const uint4 rv = lds128(wR + off);
                mma_bf16(accR[nt], aH, rv.x, rv.y);
                mma_bf16(accR[nt], aL, rv.x, rv.y);
                mma_bf16(accR[nt], aH, rv.z, rv.w);
            }
        }
    }
}

// ---------------- chunk MMA (A from registers, layer 0) ---------------------
__device__ __forceinline__ void mma_chunk_r(float accF[8][4], float accR[8][4],
                                            const uint4 AH[4], const uint4 AL[4],
                                            u32 wF, u32 wR, int g, int t)
{
#pragma unroll
    for (int kt = 0; kt < 4; kt++) {
        const u32 aH[4] = {AH[kt].x, AH[kt].y, AH[kt].z, AH[kt].w};
        const u32 aL[4] = {AL[kt].x, AL[kt].y, AL[kt].z, AL[kt].w};
#pragma unroll
        for (int nt = 0; nt < 8; nt++) {
            const u32 off = (u32)(((kt * 64 + nt * 8 + g) * 4 + t) * 16);
            const uint4 wv = lds128(wF + off);
            mma_bf16(accF[nt], aH, wv.x, wv.y);
            mma_bf16(accF[nt], aL, wv.x, wv.y);
            mma_bf16(accF[nt], aH, wv.z, wv.w);
            const uint4 rv = lds128(wR + off);
            mma_bf16(accR[nt], aH, rv.x, rv.y);
            mma_bf16(accR[nt], aL, rv.x, rv.y);
            mma_bf16(accR[nt], aH, rv.z, rv.w);
        }
    }
}

// ---------------- epilogue: bias+relu+residual -> frag-packed A planes ------
template<int NT, bool DUAL>
__device__ __forceinline__ void epilogue(float accF[][4], float accR[][4],
                                         const float* bias, u32 sb, int colbase,
                                         int w, int g, int t)
{
#pragma unroll
    for (int nt = 0; nt < NT; nt++) {
        const int c0 = colbase + nt * 8 + t * 2;
        const float b0 = __ldg(bias + c0), b1 = __ldg(bias + c0 + 1);
        float v0 = fmaxf(accF[nt][0] + b0, 0.f);
        float v1 = fmaxf(accF[nt][1] + b1, 0.f);
        float v2 = fmaxf(accF[nt][2] + b0, 0.f);
        float v3 = fmaxf(accF[nt][3] + b1, 0.f);
        const u32 fb = sb + OFF_AH + (u32)((c0 >> 4) * 4096)
                     + (u32)((w * 32 + g * 4 + ((c0 & 7) >> 1)) * 16) + (u32)(c0 & 8);
        if (DUAL) {
            v0 += accR[nt][0]; v1 += accR[nt][1];
            v2 += accR[nt][2]; v3 += accR[nt][3];
        } else {
            const u32 ph0 = lds32(fb),     pl0 = lds32(fb + APL);
            const u32 ph1 = lds32(fb + 4), pl1 = lds32(fb + 4 + APL);
            v0 += bflo(ph0) + bflo(pl0); v1 += bfhi(ph0) + bfhi(pl0);
            v2 += bflo(ph1) + bflo(pl1); v3 += bfhi(ph1) + bfhi(pl1);
        }
        u32 hh, ll;
        split2(v0, v1, hh, ll); sts32(fb, hh);     sts32(fb + APL, ll);
        split2(v2, v3, hh, ll); sts32(fb + 4, hh); sts32(fb + 4 + APL, ll);
    }
}

// ---------------- main fused MLP (pipelined) --------------------------------
__global__ void __launch_bounds__(256, 1) mlp_tc(P p)
{
    extern __shared__ char sm[];
    const u32 sb  = smem_u32(sm);
    const int tid = threadIdx.x;
    const int lane = tid & 31, warp = tid >> 5;
    const int g = lane >> 2, t = lane & 3;
    const int h   = blockIdx.y;
    const int blk = blockIdx.x;
    const int n0  = blk * 128;
    const u32 fragoff = (u32)((warp * 32 + lane) * 16);

    int* idx_s = (int*)(sm + OFF_IDX);
    if (tid < 128) idx_s[tid] = (n0 + tid < p.n) ? p.ridx[n0 + tid] : 0;

    const char* gw = (const char*)g_w + (size_t)h * HB;
    const char* a0 = (const char*)g_a0 + (size_t)blk * 196608;

    int cc = 0;
#define WBUF(i)  (sb + OFF_W + (u32)(((i) & 1) * 32768))

    // prefetch L0 (q=0, kc=0)
    {
        u32 b = WBUF(0);
        stage(b,         gw + B0, 16384, tid);
        stage(b + 16384, gw + B1, 16384, tid);
        COMMIT();
    }

    // ===== layer 0: 384(pad) -> 256, fc + res, n-quarters =====
    for (int q = 0; q < 4; q++) {
        float accF[8][4], accR[8][4];
#pragma unroll
        for (int i = 0; i < 8; i++)
#pragma unroll
            for (int j = 0; j < 4; j++) { accF[i][j] = 0.f; accR[i][j] = 0.f; }
        for (int kc = 0; kc < 6; kc++) {
            // A frags direct from gmem (issue early; completes under wait/sync)
            uint4 AH[4], AL[4];
#pragma unroll
            for (int kt = 0; kt < 4; kt++) {
                const char* ap = a0 + (size_t)((((kc * 4 + kt) * 8 + warp) * 8 + g) * 4 + t) * 16;
                AH[kt] = *(const uint4*)ap;
                AL[kt] = *(const uint4*)(ap + 98304);
            }
            WAITG0();
            __syncthreads();
            u32 nxt = WBUF(cc + 1);
            if (kc < 5) {
                stage(nxt,         gw + B0 + ((kc + 1) * 4 + q) * 16384, 16384, tid);
                stage(nxt + 16384, gw + B1 + ((kc + 1) * 4 + q) * 16384, 16384, tid);
                COMMIT();
            } else if (q < 3) {
                stage(nxt,         gw + B0 + (q + 1) * 16384, 16384, tid);
                stage(nxt + 16384, gw + B1 + (q + 1) * 16384, 16384, tid);
                COMMIT();
            } else {
                stage(nxt, gw + B2, 32768, tid);
                COMMIT();
            }
            const u32 wF = WBUF(cc);
            mma_chunk_r(accF, accR, AH, AL, wF, wF + 16384, g, t);
            cc++;
        }
        __syncthreads();
        epilogue<8, true>(accF, accR, p.fcb0 + h * 256, sb, q * 64, warp, g, t);
        __syncthreads();
    }

    // ===== layers 1-3: 256 -> 256, identity residual =====
    for (int l = 0; l < 3; l++) {
        const float* bias = (l == 0 ? p.fcb1 : l == 1 ? p.fcb2 : p.fcb3) + h * 256;
        const char* wl = gw + B2 + (size_t)l * 262144;
        float acc[32][4];
#pragma unroll
        for (int i = 0; i < 32; i++)
#pragma unroll
            for (int j = 0; j < 4; j++) acc[i][j] = 0.f;
        for (int c = 0; c < 8; c++) {
            WAITG0();
            __syncthreads();
            u32 nxt = WBUF(cc + 1);
            if (c < 7) {
                stage(nxt, wl + (c + 1) * 32768, 32768, tid);
                COMMIT();
            } else if (l < 2) {
                stage(nxt, wl + 262144, 32768, tid);
                COMMIT();
            } else {
                stage(nxt,         gw + B5, 16384, tid);
                stage(nxt + 16384, gw + B6, 16384, tid);
                COMMIT();
            }
            mma_chunk_s<2, 32, false>(acc, acc, sb + OFF_AH + c * 8192 + fragoff,
                                      WBUF(cc), 0, 256, g, t);
            cc++;
        }
        __syncthreads();
        epilogue<32, false>(acc, acc, bias, sb, 0, warp, g, t);
        __syncthreads();
    }

    // ===== layer 4: 256 -> 128, fc + res =====
    {
        float accF[16][4], accR[16][4];
#pragma unroll
        for (int i = 0; i < 16; i++)
#pragma unroll
            for (int j = 0; j < 4; j++) { accF[i][j] = 0.f; accR[i][j] = 0.f; }
        for (int c = 0; c < 8; c++) {
            WAITG0();
            __syncthreads();
            u32 nxt = WBUF(cc + 1);
            if (c < 7) {
                stage(nxt,         gw + B5 + (c + 1) * 16384, 16384, tid);
                stage(nxt + 16384, gw + B6 + (c + 1) * 16384, 16384, tid);
                COMMIT();
            } else {
                stage(nxt, gw + B7, 16384, tid);
                COMMIT();
            }
            const u32 wF = WBUF(cc);
            mma_chunk_s<2, 16, true>(accF, accR, sb + OFF_AH + c * 8192 + fragoff,
                                     wF, wF + 16384, 128, g, t);
            cc++;
        }
        __syncthreads();
        epilogue<16, true>(accF, accR, p.fcb4 + h * 128, sb, 0, warp, g, t);
        __syncthreads();
    }

    // ===== layer 5: 128 -> 128, identity =====
    {
        float acc[16][4];
#pragma unroll
        for (int i = 0; i < 16; i++)
#pragma unroll
            for (int j = 0; j < 4; j++) acc[i][j] = 0.f;
        for (int c = 0; c < 4; c++) {
            WAITG0();
            __syncthreads();
            u32 nxt = WBUF(cc + 1);
            if (c < 3) {
                stage(nxt, gw + B7 + (c + 1) * 16384, 16384, tid);
                COMMIT();
            } else {
                stage(nxt,        gw + B8, 8192, tid);
                stage(nxt + 8192, gw + B9, 8192, tid);
                COMMIT();
            }
            mma_chunk_s<2, 16, false>(acc, acc, sb + OFF_AH + c * 8192 + fragoff,
                                      WBUF(cc), 0, 128, g, t);
            cc++;
        }
        __syncthreads();
        epilogue<16, false>(acc, acc, p.fcb5 + h * 128, sb, 0, warp, g, t);
        __syncthreads();
    }

    // ===== layer 6: 128 -> 64, fc + res =====
    {
        float accF[8][4], accR[8][4];
#pragma unroll
        for (int i = 0; i < 8; i++)
#pragma unroll
            for (int j = 0; j < 4; j++) { accF[i][j] = 0.f; accR[i][j] = 0.f; }
        for (int c = 0; c < 4; c++) {
            WAITG0();
            __syncthreads();
            if (c < 3) {
                u32 nxt = WBUF(cc + 1);
                stage(nxt,        gw + B8 + (c + 1) * 8192, 8192, tid);
                stage(nxt + 8192, gw + B9 + (c + 1) * 8192, 8192, tid);
                COMMIT();
            }
            const u32 wF = WBUF(cc);
            mma_chunk_s<2, 8, true>(accF, accR, sb + OFF_AH + c * 8192 + fragoff,
                                    wF, wF + 8192, 64, g, t);
            cc++;
        }
        __syncthreads();
        epilogue<8, true>(accF, accR, p.fcb6 + h * 64, sb, 0, warp, g, t);
        __syncthreads();
    }

    // ===== output head: gate = h . outW + outb =====
    if (tid < 128) {
        const int r = tid, e = n0 + r;
        if (e < p.n) {
            const int w2 = r >> 4, g2 = r & 7, rh = (r & 15) >> 3;
            float acc = 0.f;
#pragma unroll
            for (int c = 0; c < 64; c += 2) {
                const u32 fb = sb + OFF_AH + (u32)((c >> 4) * 4096)
                             + (u32)((w2 * 32 + g2 * 4 + ((c & 7) >> 1)) * 16)
                             + (u32)((c & 8) + rh * 4);
                const u32 ph = lds32(fb), pl = lds32(fb + APL);
                acc = fmaf(bflo(ph) + bflo(pl), __ldg(p.outW + h * 64 + c), acc);
                acc = fmaf(bfhi(ph) + bfhi(pl), __ldg(p.outW + h * 64 + c + 1), acc);
            }
            const float gate = acc + __ldg(p.outb + h);
            g_gate[h * p.n + e] = gate;
            atomicMax(&g_segmax[h * p.c + idx_s[r]], fkey(gate));
        }
    }
}

// ---------------- segment softmax epilogue ---------------------------------
__global__ void init_seg(int total)
{
    const int i = blockIdx.x * blockDim.x + threadIdx.x;
    if (i < total) { g_segmax[i] = 0u; g_segsum[i] = 0.f; }
}

__global__ void exp_kernel(const int* __restrict__ ridx, int n, int c)
{
    const int i = blockIdx.x * blockDim.x + threadIdx.x;
    if (i >= NH * n) return;
    const int hh = i / n;
    const int nn = i - hh * n;
    const int r  = ridx[nn];
    const float m = funkey(g_segmax[hh * c + r]);
    const float e = expf(g_gate[i] - m);
    g_gate[i] = e;
    atomicAdd(&g_segsum[hh * c + r], e);
}

__global__ void out_kernel(const int* __restrict__ ridx,
                           float* __restrict__ out, int n, int c)
{
    const int nn = blockIdx.x * blockDim.x + threadIdx.x;
    if (nn >= n) return;
    const int r = ridx[nn];
    float s = 0.f;
#pragma unroll
    for (int hh = 0; hh < NH; ++hh)
        s += g_gate[hh * n + nn] / (g_segsum[hh * c + r] + 1e-13f);
    out[nn] = s * (1.0f / 3.0f);
}

extern "C" void kernel_launch(void* const* d_in, const int* in_sizes, int n_in,
                              void* d_out, int out_size)
{
    P p;
    p.elem  = (const float*)d_in[0];
    p.ridx  = (const int*)  d_in[1];
    p.remb  = (const float*)d_in[2];
    p.fcW0  = (const float*)d_in[3];  p.fcb0 = (const float*)d_in[4];
    p.fcW1  = (const float*)d_in[5];  p.fcb1 = (const float*)d_in[6];
    p.fcW2  = (const float*)d_in[7];  p.fcb2 = (const float*)d_in[8];
    p.fcW3  = (const float*)d_in[9];  p.fcb3 = (const float*)d_in[10];
    p.fcW4  = (const float*)d_in[11]; p.fcb4 = (const float*)d_in[12];
    p.fcW5  = (const float*)d_in[13]; p.fcb5 = (const float*)d_in[14];
    p.fcW6  = (const float*)d_in[15]; p.fcb6 = (const float*)d_in[16];
    p.resW0 = (const float*)d_in[17];
    p.resW4 = (const float*)d_in[18];
    p.resW6 = (const float*)d_in[19];
    p.outW  = (const float*)d_in[20];
    p.outb  = (const float*)d_in[21];
    p.n = in_sizes[1];
    p.c = in_sizes[2] / 128;

    static bool init_done = false;
    if (!init_done) {
        cudaFuncSetAttribute(mlp_tc, cudaFuncAttributeMaxDynamicSharedMemorySize, SMEMSZ);
        init_done = true;
    }

    const int nblk = (p.n + 127) / 128;

    prep_w<<<dim3(480, NH), 256>>>(p);
    prep_a0<<<dim3(24, nblk), 256>>>(p);

    const int segs = NH * p.c;
    init_seg<<<(segs + 255) / 256, 256>>>(segs);

    mlp_tc<<<dim3(nblk, NH), 256, SMEMSZ>>>(p);

    const int tot = NH * p.n;
    exp_kernel<<<(tot + 255) / 256, 256>>>(p.ridx, p.n, p.c);
    out_kernel<<<(p.n + 255) / 256, 256>>>(p.ridx, (float*)d_out, p.n, p.c);
}

// round 8
// speedup vs baseline: 3.9032x; 1.0102x over previous
#include <cuda_runtime.h>
#include <cuda_bf16.h>
#include <math.h>
#include <stdint.h>

typedef uint32_t u32;

#define NH 3
#define NEMAX 200000
#define NCMAX 100000
#define BLKMAX 1563          // ceil(200000/128)

// ---------------- device scratch -----------------------------------------
__device__ float    g_gate[NH * NEMAX];
__device__ unsigned g_segmax[NH * NCMAX];
__device__ float    g_segsum[NH * NCMAX];

// frag-packed weights, per head 983040 bf16 (byte stride HB)
#define HB 1966080
__device__ __align__(16) __nv_bfloat16 g_w[3 * 983040];
// frag-packed layer0 activations: per block 196608 B (hi plane 98304 + lo plane)
__device__ uint4 g_a0[(size_t)BLKMAX * 12288];

// matrix byte offsets within a head
#define B0 0
#define B1 393216
#define B2 786432
#define B5 1572864
#define B6 1703936
#define B7 1835008
#define B8 1900544
#define B9 1933312

// ---------------- smem offsets (bytes) -------------------------------------
#define APL     65536        // A plane size
#define OFF_AH  0
#define OFF_AL  65536
#define OFF_W   131072       // weight ping-pong, 2 x 32768
#define OFF_IDX 196608
#define SMEMSZ  197120

#define NTH 512

// ---------------- helpers -------------------------------------------------
__device__ __forceinline__ u32 smem_u32(const void* p) {
    u32 a;
    asm("{ .reg .u64 t; cvta.to.shared.u64 t, %1; cvt.u32.u64 %0, t; }" : "=r"(a) : "l"(p));
    return a;
}
__device__ __forceinline__ u32 lds32(u32 a) {
    u32 v; asm volatile("ld.shared.b32 %0, [%1];" : "=r"(v) : "r"(a)); return v;
}
__device__ __forceinline__ uint4 lds128(u32 a) {
    uint4 v;
    asm volatile("ld.shared.v4.b32 {%0,%1,%2,%3}, [%4];"
                 : "=r"(v.x), "=r"(v.y), "=r"(v.z), "=r"(v.w) : "r"(a));
    return v;
}
__device__ __forceinline__ void sts32(u32 a, u32 v) {
    asm volatile("st.shared.b32 [%0], %1;" :: "r"(a), "r"(v) : "memory");
}
__device__ __forceinline__ void cp16(u32 dst, const void* src) {
    asm volatile("cp.async.cg.shared.global [%0], [%1], 16;" :: "r"(dst), "l"(src));
}
#define COMMIT()  asm volatile("cp.async.commit_group;" ::: "memory")
#define WAITG0()  asm volatile("cp.async.wait_group 0;" ::: "memory")

__device__ __forceinline__ void mma_bf16(float c[4], const u32 a[4], u32 b0, u32 b1) {
    asm volatile(
        "mma.sync.aligned.m16n8k16.row.col.f32.bf16.bf16.f32 "
        "{%0,%1,%2,%3}, {%4,%5,%6,%7}, {%8,%9}, {%0,%1,%2,%3};"
        : "+f"(c[0]), "+f"(c[1]), "+f"(c[2]), "+f"(c[3])
        : "r"(a[0]), "r"(a[1]), "r"(a[2]), "r"(a[3]), "r"(b0), "r"(b1));
}

__device__ __forceinline__ float bflo(u32 v) {
    return __bfloat162float(__ushort_as_bfloat16((unsigned short)(v & 0xFFFF)));
}
__device__ __forceinline__ float bfhi(u32 v) {
    return __bfloat162float(__ushort_as_bfloat16((unsigned short)(v >> 16)));
}
__device__ __forceinline__ void split2(float v0, float v1, u32& hi, u32& lo) {
    __nv_bfloat16 h0 = __float2bfloat16(v0);
    __nv_bfloat16 h1 = __float2bfloat16(v1);
    __nv_bfloat16 l0 = __float2bfloat16(v0 - __bfloat162float(h0));
    __nv_bfloat16 l1 = __float2bfloat16(v1 - __bfloat162float(h1));
    hi = (u32)__bfloat16_as_ushort(h0) | ((u32)__bfloat16_as_ushort(h1) << 16);
    lo = (u32)__bfloat16_as_ushort(l0) | ((u32)__bfloat16_as_ushort(l1) << 16);
}
__device__ __forceinline__ unsigned fkey(float f) {
    unsigned u = __float_as_uint(f);
    return (u & 0x80000000u) ? ~u : (u | 0x80000000u);
}
__device__ __forceinline__ float funkey(unsigned u) {
    return (u & 0x80000000u) ? __uint_as_float(u & 0x7FFFFFFFu) : __uint_as_float(~u);
}

__device__ __forceinline__ void stage(u32 sdst, const void* src, int bytes, int tid) {
    const char* s = (const char*)src;
    for (int i = tid * 16; i < bytes; i += NTH * 16) cp16(sdst + i, s + i);
}

struct P {
    const float* elem; const int* ridx; const float* remb;
    const float *fcW0, *fcb0, *fcW1, *fcb1, *fcW2, *fcb2, *fcW3, *fcb3;
    const float *fcW4, *fcb4, *fcW5, *fcb5, *fcW6, *fcb6;
    const float *resW0, *resW4, *resW6, *outW, *outb;
    int n, c;
};

// ---------------- prep: weights -> frag-packed layout ----------------------
// frag uint4 = {hi(k0,k0+1), hi(k0+8,k0+9), lo(k0,k0+1), lo(k0+8,k0+9)}
__global__ void prep_w(P p)
{
    const int fid = blockIdx.x * 256 + threadIdx.x;
    const int h = blockIdx.y;
    if (fid >= 122880) return;
    const int fo[11] = {0,24576,49152,65536,81920,98304,106496,114688,118784,120832,122880};
    int m = 0;
    while (fid >= fo[m + 1]) m++;
    const int local = fid - fo[m];
    int K, N; const float* W;
    switch (m) {
        case 0: K=328; N=256; W=p.fcW0;  break;
        case 1: K=328; N=256; W=p.resW0; break;
        case 2: K=256; N=256; W=p.fcW1;  break;
        case 3: K=256; N=256; W=p.fcW2;  break;
        case 4: K=256; N=256; W=p.fcW3;  break;
        case 5: K=256; N=128; W=p.fcW4;  break;
        case 6: K=256; N=128; W=p.resW4; break;
        case 7: K=128; N=128; W=p.fcW5;  break;
        case 8: K=128; N=64;  W=p.fcW6;  break;
        default:K=128; N=64;  W=p.resW6; break;
    }
    int t, n, kt, kc;
    if (m < 2) {   // layer0: [kc][q][kt][64n][4t]
        t = local & 3;
        const int nl = (local >> 2) & 63;
        kt = (local >> 8) & 3;
        const int blkq = local >> 10;
        const int q = blkq & 3;
        kc = blkq >> 2;
        n = q * 64 + nl;
    } else {       // [kc][kt][N][4t]
        t = local & 3;
        int r = local >> 2;
        n = r % N; r /= N;
        kt = r & 3; kc = r >> 2;
    }
    const int k0 = kc * 64 + kt * 16 + 2 * t;
    const float* Wh = W + (size_t)h * K * N;
    const float v0 = (k0     < K) ? Wh[(size_t)k0 * N + n]       : 0.f;
    const float v1 = (k0 + 1 < K) ? Wh[(size_t)(k0 + 1) * N + n] : 0.f;
    const float v8 = (k0 + 8 < K) ? Wh[(size_t)(k0 + 8) * N + n] : 0.f;
    const float v9 = (k0 + 9 < K) ? Wh[(size_t)(k0 + 9) * N + n] : 0.f;
    uint4 o;
    u32 l0, l1;
    split2(v0, v1, o.x, l0);
    split2(v8, v9, o.y, l1);
    o.z = l0; o.w = l1;
    *(uint4*)((char*)g_w + (size_t)h * HB + (size_t)fid * 16) = o;
}

// ---------------- prep: layer0 input -> frag-packed g_a0 -------------------
__device__ __forceinline__ void ld2(const P& p, int e, int idx, int f, float& x, float& y)
{
    if (f < 200)      { x = p.elem[(size_t)e * 200 + f]; y = p.elem[(size_t)e * 200 + f + 1]; }
    else if (f < 328) { const float* r = p.remb + (size_t)idx * 128 + (f - 200); x = r[0]; y = r[1]; }
    else              { x = 0.f; y = 0.f; }
}

__global__ void prep_a0(P p)
{
    const int fi  = blockIdx.x * 256 + threadIdx.x;    // 0..6143
    const int blk = blockIdx.y;
    const int t  = fi & 3;
    const int g  = (fi >> 2) & 7;
    const int w  = (fi >> 5) & 7;
    const int kt = (fi >> 8) & 3;
    const int kc = fi >> 10;
    const int k0 = kc * 64 + kt * 16 + 2 * t;
    float v[2][4];
#pragma unroll
    for (int row = 0; row < 2; row++) {
        const int e = blk * 128 + w * 16 + g + row * 8;
        if (e < p.n) {
            const int idx = p.ridx[e];
            ld2(p, e, idx, k0,     v[row][0], v[row][1]);
            ld2(p, e, idx, k0 + 8, v[row][2], v[row][3]);
        } else {
            v[row][0] = v[row][1] = v[row][2] = v[row][3] = 0.f;
        }
    }
    uint4 H, L;
    split2(v[0][0], v[0][1], H.x, L.x);
    split2(v[1][0], v[1][1], H.y, L.y);
    split2(v[0][2], v[0][3], H.z, L.z);
    split2(v[1][2], v[1][3], H.w, L.w);
    char* dst = (char*)g_a0 + (size_t)blk * 196608 + (size_t)fi * 16;
    *(uint4*)dst = H;
    *(uint4*)(dst + 98304) = L;
}

// ---------------- chunk MMA (A from smem planes) ----------------------------
// each warp: 16 rows (rg) x NT*8 cols starting at colOff
template<int KT, int NT, bool DUAL>
__device__ __forceinline__ void mma_chunk_s(float accF[][4], float accR[][4],
                                            u32 abase, u32 wF, u32 wR,
                                            int N, int colOff, int g, int t)
{
#pragma unroll
    for (int kt = 0; kt < KT; kt++) {
        const uint4 ahv = lds128(abase + kt * 4096);
        const uint4 alv = lds128(abase + kt * 4096 + APL);
        const u32 aH[4] = {ahv.x, ahv.y, ahv.z, ahv.w};
        const u32 aL[4] = {alv.x, alv.y, alv.z, alv.w};
#pragma unroll
        for (int nt = 0; nt < NT; nt++) {
            const u32 off = (u32)(((kt * N + colOff + nt * 8 + g) * 4 + t) * 16);
            const uint4 wv = lds128(wF + off);
            mma_bf16(accF[nt], aH, wv.x, wv.y);
            mma_bf16(accF[nt], aL, wv.x, wv.y);
            mma_bf16(accF[nt], aH, wv.z, wv.w);
            if (DUAL) {
                const uint4 rv = lds128(wR + off);
                mma_bf16(accR[nt], aH, rv.x, rv.y);
                mma_bf16(accR[nt], aL, rv.x, rv.y);
                mma_bf16(accR[nt], aH, rv.z, rv.w);
            }
        }
    }
}

// ---------------- chunk MMA (A from registers, layer 0) ---------------------
__device__ __forceinline__ void mma_chunk_r(float accF[4][4], float accR[4][4],
                                            const uint4 AH[4], const uint4 AL[4],
                                            u32 wF, u32 wR, int colOff, int g, int t)
{
#pragma unroll
    for (int kt = 0; kt < 4; kt++) {
        const u32 aH[4] = {AH[kt].x, AH[kt].y, AH[kt].z, AH[kt].w};
        const u32 aL[4] = {AL[kt].x, AL[kt].y, AL[kt].z, AL[kt].w};
#pragma unroll
        for (int nt = 0; nt < 4; nt++) {
            const u32 off = (u32)(((kt * 64 + colOff + nt * 8 + g) * 4 + t) * 16);
            const uint4 wv = lds128(wF + off);
            mma_bf16(accF[nt], aH, wv.x, wv.y);
            mma_bf16(accF[nt], aL, wv.x, wv.y);
            mma_bf16(accF[nt], aH, wv.z, wv.w);
            const uint4 rv = lds128(wR + off);
            mma_bf16(accR[nt], aH, rv.x, rv.y);
            mma_bf16(accR[nt], aL, rv.x, rv.y);
            mma_bf16(accR[nt], aH, rv.z, rv.w);
        }
    }
}

// ---------------- epilogue: bias+relu+residual -> frag-packed A planes ------
template<int NT, bool DUAL>
__device__ __forceinline__ void epilogue(float accF[][4], float accR[][4],
                                         const float* bias, u32 sb, int colbase,
                                         int rg, int g, int t)
{
#pragma unroll
    for (int nt = 0; nt < NT; nt++) {
        const int c0 = colbase + nt * 8 + t * 2;
        const float b0 = __ldg(bias + c0), b1 = __ldg(bias + c0 + 1);
        float v0 = fmaxf(accF[nt][0] + b0, 0.f);
        float v1 = fmaxf(accF[nt][1] + b1, 0.f);
        float v2 = fmaxf(accF[nt][2] + b0, 0.f);
        float v3 = fmaxf(accF[nt][3] + b1, 0.f);
        const u32 fb = sb + OFF_AH + (u32)((c0 >> 4) * 4096)
                     + (u32)((rg * 32 + g * 4 + ((c0 & 7) >> 1)) * 16) + (u32)(c0 & 8);
        if (DUAL) {
            v0 += accR[nt][0]; v1 += accR[nt][1];
            v2 += accR[nt][2]; v3 += accR[nt][3];
        } else {
            const u32 ph0 = lds32(fb),     pl0 = lds32(fb + APL);
            const u32 ph1 = lds32(fb + 4), pl1 = lds32(fb + 4 + APL);
            v0 += bflo(ph0) + bflo(pl0); v1 += bfhi(ph0) + bfhi(pl0);
            v2 += bflo(ph1) + bflo(pl1); v3 += bfhi(ph1) + bfhi(pl1);
        }
        u32 hh, ll;
        split2(v0, v1, hh, ll); sts32(fb, hh);     sts32(fb + APL, ll);
        split2(v2, v3, hh, ll); sts32(fb + 4, hh); sts32(fb + 4 + APL, ll);
    }
}

// ---------------- main fused MLP (pipelined, 512 threads) -------------------
__global__ void __launch_bounds__(NTH, 1) mlp_tc(P p)
{
    extern __shared__ char sm[];
    const u32 sb  = smem_u32(sm);
    const int tid = threadIdx.x;
    const int lane = tid & 31, warp = tid >> 5;
    const int rg = warp >> 1;            // row group 0-7 (16 rows each)
    const int ch = warp & 1;             // column half
    const int g = lane >> 2, t = lane & 3;
    const int h   = blockIdx.y;
    const int blk = blockIdx.x;
    const int n0  = blk * 128;
    const u32 fragoff = (u32)((rg * 32 + lane) * 16);

    int* idx_s = (int*)(sm + OFF_IDX);
    if (tid < 128) idx_s[tid] = (n0 + tid < p.n) ? p.ridx[n0 + tid] : 0;

    const char* gw = (const char*)g_w + (size_t)h * HB;
    const char* a0 = (const char*)g_a0 + (size_t)blk * 196608;

    int cc = 0;
#define WBUF(i)  (sb + OFF_W + (u32)(((i) & 1) * 32768))

    // prefetch L0 (q=0, kc=0)
    {
        u32 b = WBUF(0);
        stage(b,         gw + B0, 16384, tid);
        stage(b + 16384, gw + B1, 16384, tid);
        COMMIT();
    }

    // ===== layer 0: 384(pad) -> 256, fc + res, n-quarters =====
    for (int q = 0; q < 4; q++) {
        float accF[4][4], accR[4][4];
#pragma unroll
        for (int i = 0; i < 4; i++)
#pragma unroll
            for (int j = 0; j < 4; j++) { accF[i][j] = 0.f; accR[i][j] = 0.f; }
        for (int kc = 0; kc < 6; kc++) {
            // A frags direct from gmem (issue early; completes under wait/sync)
            uint4 AH[4], AL[4];
#pragma unroll
            for (int kt = 0; kt < 4; kt++) {
                const char* ap = a0 + (size_t)((((kc * 4 + kt) * 8 + rg) * 8 + g) * 4 + t) * 16;
                AH[kt] = *(const uint4*)ap;
                AL[kt] = *(const uint4*)(ap + 98304);
            }
            WAITG0();
            __syncthreads();
            u32 nxt = WBUF(cc + 1);
            if (kc < 5) {
                stage(nxt,         gw + B0 + ((kc + 1) * 4 + q) * 16384, 16384, tid);
                stage(nxt + 16384, gw + B1 + ((kc + 1) * 4 + q) * 16384, 16384, tid);
                COMMIT();
            } else if (q < 3) {
                stage(nxt,         gw + B0 + (q + 1) * 16384, 16384, tid);
                stage(nxt + 16384, gw + B1 + (q + 1) * 16384, 16384, tid);
                COMMIT();
            } else {
                stage(nxt, gw + B2, 32768, tid);
                COMMIT();
            }
            const u32 wF = WBUF(cc);
            mma_chunk_r(accF, accR, AH, AL, wF, wF + 16384, ch * 32, g, t);
            cc++;
        }
        __syncthreads();
        epilogue<4, true>(accF, accR, p.fcb0 + h * 256, sb, q * 64 + ch * 32, rg, g, t);
        __syncthreads();
    }

    // ===== layers 1-3: 256 -> 256, identity residual =====
    for (int l = 0; l < 3; l++) {
        const float* bias = (l == 0 ? p.fcb1 : l == 1 ? p.fcb2 : p.fcb3) + h * 256;
        const char* wl = gw + B2 + (size_t)l * 262144;
        float acc[16][4];
#pragma unroll
        for (int i = 0; i < 16; i++)
#pragma unroll
            for (int j = 0; j < 4; j++) acc[i][j] = 0.f;
        for (int c = 0; c < 8; c++) {
            WAITG0();
            __syncthreads();
            u32 nxt = WBUF(cc + 1);
            if (c < 7) {
                stage(nxt, wl + (c + 1) * 32768, 32768, tid);
                COMMIT();
            } else if (l < 2) {
                stage(nxt, wl + 262144, 32768, tid);
                COMMIT();
            } else {
                stage(nxt,         gw + B5, 16384, tid);
                stage(nxt + 16384, gw + B6, 16384, tid);
                COMMIT();
            }
            mma_chunk_s<2, 16, false>(acc, acc, sb + OFF_AH + c * 8192 + fragoff,
                                      WBUF(cc), 0, 256, ch * 128, g, t);
            cc++;
        }
        __syncthreads();
        epilogue<16, false>(acc, acc, bias, sb, ch * 128, rg, g, t);
        __syncthreads();
    }

    // ===== layer 4: 256 -> 128, fc + res =====
    {
        float accF[8][4], accR[8][4];
#pragma unroll
        for (int i = 0; i < 8; i++)
#pragma unroll
            for (int j = 0; j < 4; j++) { accF[i][j] = 0.f; accR[i][j] = 0.f; }
        for (int c = 0; c < 8; c++) {
            WAITG0();
            __syncthreads();
            u32 nxt = WBUF(cc + 1);
            if (c < 7) {
                stage(nxt,         gw + B5 + (c + 1) * 16384, 16384, tid);
                stage(nxt + 16384, gw + B6 + (c + 1) * 16384, 16384, tid);
                COMMIT();
            } else {
                stage(nxt, gw + B7, 16384, tid);
                COMMIT();
            }
            const u32 wF = WBUF(cc);
            mma_chunk_s<2, 8, true>(accF, accR, sb + OFF_AH + c * 8192 + fragoff,
                                    wF, wF + 16384, 128, ch * 64, g, t);
            cc++;
        }
        __syncthreads();
        epilogue<8, true>(accF, accR, p.fcb4 + h * 128, sb, ch * 64, rg, g, t);
        __syncthreads();
    }

    // ===== layer 5: 128 -> 128, identity =====
    {
        float acc[8][4];
#pragma unroll
        for (int i = 0; i < 8; i++)
#pragma unroll
            for (int j = 0; j < 4; j++) acc[i][j] = 0.f;
        for (int c = 0; c < 4; c++) {
            WAITG0();
            __syncthreads();
            u32 nxt = WBUF(cc + 1);
            if (c < 3) {
                stage(nxt, gw + B7 + (c + 1) * 16384, 16384, tid);
                COMMIT();
            } else {
                stage(nxt,        gw + B8, 8192, tid);
                stage(nxt + 8192, gw + B9, 8192, tid);
                COMMIT();
            }
            mma_chunk_s<2, 8, false>(acc, acc, sb + OFF_AH + c * 8192 + fragoff,
                                     WBUF(cc), 0, 128, ch * 64, g, t);
            cc++;
        }
        __syncthreads();
        epilogue<8, false>(acc, acc, p.fcb5 + h * 128, sb, ch * 64, rg, g, t);
        __syncthreads();
    }

    // ===== layer 6: 128 -> 64, fc + res =====
    {
        float accF[4][4], accR[4][4];
#pragma unroll
        for (int i = 0; i < 4; i++)
#pragma unroll
            for (int j = 0; j < 4; j++) { accF[i][j] = 0.f; accR[i][j] = 0.f; }
        for (int c = 0; c < 4; c++) {
            WAITG0();
            __syncthreads();
            if (c < 3) {
                u32 nxt = WBUF(cc + 1);
                stage(nxt,        gw + B8 + (c + 1) * 8192, 8192, tid);
                stage(nxt + 8192, gw + B9 + (c + 1) * 8192, 8192, tid);
                COMMIT();
            }
            const u32 wF = WBUF(cc);
            mma_chunk_s<2, 4, true>(accF, accR, sb + OFF_AH + c * 8192 + fragoff,
                                    wF, wF + 8192, 64, ch * 32, g, t);
            cc++;
        }
        __syncthreads();
        epilogue<4, true>(accF, accR, p.fcb6 + h * 64, sb, ch * 32, rg, g, t);
        __syncthreads();
    }

    // ===== output head: gate = h . outW + outb =====
    if (tid < 128) {
        const int r = tid, e = n0 + r;
        if (e < p.n) {
            const int w2 = r >> 4, g2 = r & 7, rh = (r & 15) >> 3;
            float acc = 0.f;
#pragma unroll
            for (int c = 0; c < 64; c += 2) {
                const u32 fb = sb + OFF_AH + (u32)((c >> 4) * 4096)
                             + (u32)((w2 * 32 + g2 * 4 + ((c & 7) >> 1)) * 16)
                             + (u32)((c & 8) + rh * 4);
                const u32 ph = lds32(fb), pl = lds32(fb + APL);
                acc = fmaf(bflo(ph) + bflo(pl), __ldg(p.outW + h * 64 + c), acc);
                acc = fmaf(bfhi(ph) + bfhi(pl), __ldg(p.outW + h * 64 + c + 1), acc);
            }
            const float gate = acc + __ldg(p.outb + h);
            g_gate[h * p.n + e] = gate;
            atomicMax(&g_segmax[h * p.c + idx_s[r]], fkey(gate));
        }
    }
}

// ---------------- segment softmax epilogue ---------------------------------
__global__ void init_seg(int total)
{
    const int i = blockIdx.x * blockDim.x + threadIdx.x;
    if (i < total) { g_segmax[i] = 0u; g_segsum[i] = 0.f; }
}

__global__ void exp_kernel(const int* __restrict__ ridx, int n, int c)
{
    const int i = blockIdx.x * blockDim.x + threadIdx.x;
    if (i >= NH * n) return;
    const int hh = i / n;
    const int nn = i - hh * n;
    const int r  = ridx[nn];
    const float m = funkey(g_segmax[hh * c + r]);
    const float e = expf(g_gate[i] - m);
    g_gate[i] = e;
    atomicAdd(&g_segsum[hh * c + r], e);
}

__global__ void out_kernel(const int* __restrict__ ridx,
                           float* __restrict__ out, int n, int c)
{
    const int nn = blockIdx.x * blockDim.x + threadIdx.x;
    if (nn >= n) return;
    const int r = ridx[nn];
    float s = 0.f;
#pragma unroll
    for (int hh = 0; hh < NH; ++hh)
        s += g_gate[hh * n + nn] / (g_segsum[hh * c + r] + 1e-13f);
    out[nn] = s * (1.0f / 3.0f);
}

extern "C" void kernel_launch(void* const* d_in, const int* in_sizes, int n_in,
                              void* d_out, int out_size)
{
    P p;
    p.elem  = (const float*)d_in[0];
    p.ridx  = (const int*)  d_in[1];
    p.remb  = (const float*)d_in[2];
    p.fcW0  = (const float*)d_in[3];  p.fcb0 = (const float*)d_in[4];
    p.fcW1  = (const float*)d_in[5];  p.fcb1 = (const float*)d_in[6];
    p.fcW2  = (const float*)d_in[7];  p.fcb2 = (const float*)d_in[8];
    p.fcW3  = (const float*)d_in[9];  p.fcb3 = (const float*)d_in[10];
    p.fcW4  = (const float*)d_in[11]; p.fcb4 = (const float*)d_in[12];
    p.fcW5  = (const float*)d_in[13]; p.fcb5 = (const float*)d_in[14];
    p.fcW6  = (const float*)d_in[15]; p.fcb6 = (const float*)d_in[16];
    p.resW0 = (const float*)d_in[17];
    p.resW4 = (const float*)d_in[18];
    p.resW6 = (const float*)d_in[19];
    p.outW  = (const float*)d_in[20];
    p.outb  = (const float*)d_in[21];
    p.n = in_sizes[1];
    p.c = in_sizes[2] / 128;

    static bool init_done = false;
    if (!init_done) {
        cudaFuncSetAttribute(mlp_tc, cudaFuncAttributeMaxDynamicSharedMemorySize, SMEMSZ);
        init_done = true;
    }

    const int nblk = (p.n + 127) / 128;

    prep_w<<<dim3(480, NH), 256>>>(p);
    prep_a0<<<dim3(24, nblk), 256>>>(p);

    const int segs = NH * p.c;
    init_seg<<<(segs + 255) / 256, 256>>>(segs);

    mlp_tc<<<dim3(nblk, NH), NTH, SMEMSZ>>>(p);

    const int tot = NH * p.n;
    exp_kernel<<<(tot + 255) / 256, 256>>>(p.ridx, p.n, p.c);
    out_kernel<<<(p.n + 255) / 256, 256>>>(p.ridx, (float*)d_out, p.n, p.c);
}